// round 2
// baseline (speedup 1.0000x reference)
#include <cuda_runtime.h>
#include <math.h>

constexpr int B   = 128;
constexpr int L   = 128;
constexpr int D   = 300;
constexpr int MD  = 50;
constexpr int GIN = 350;
constexpr int GINP= 352;
constexpr int HD  = 256;
constexpr int G3  = 768;
constexpr int H   = 512;
constexpr int R   = 128;
constexpr int T   = 4;
constexpr int NK  = 4;
constexpr int ML  = B * L;

// ---- static scratch ----
__device__ float d_x[ML * GINP];
__device__ float d_Wp[2 * G3 * GINP];
__device__ float d_gi[2 * (size_t)ML * G3];
__device__ float d_h[2 * 2 * B * HD];
__device__ float d_ctx[(size_t)ML * H];
__device__ float d_wtab[ML];
__device__ float d_fk[NK * ML * T];
__device__ float d_alpha[NK * ML * T];
__device__ float d_sp[NK * ML];
__device__ float d_spsum[NK * B];
__device__ float d_sv[NK * B * H];
__device__ float d_tbeff[NK * T];
__device__ float d_scores[B * 3];

__device__ __forceinline__ float sigm(float x) { return 1.f / (1.f + expf(-x)); }
__device__ __forceinline__ float lse4(float v0, float v1, float v2, float v3) {
    float mx = fmaxf(fmaxf(v0, v1), fmaxf(v2, v3));
    return mx + logf(expf(v0 - mx) + expf(v1 - mx) + expf(v2 - mx) + expf(v3 - mx));
}

// ---- prep ----
__global__ void prep_x(const float* __restrict__ sents, const float* __restrict__ mtab,
                       const int* __restrict__ masks) {
    const int row = blockIdx.x;
    const int msk = masks[row];
    for (int k = threadIdx.x; k < GINP; k += blockDim.x) {
        float v;
        if (k < D)        v = sents[(size_t)row * D + k];
        else if (k < GIN) v = mtab[msk * MD + (k - D)];
        else              v = 0.f;
        d_x[(size_t)row * GINP + k] = v;
    }
}

__global__ void prep_W(const float* __restrict__ Wf, const float* __restrict__ Wb) {
    const int g = blockIdx.x, dd = blockIdx.y;
    const float* W = dd ? Wb : Wf;
    for (int k = threadIdx.x; k < GINP; k += blockDim.x)
        d_Wp[((size_t)dd * G3 + g) * GINP + k] = (k < GIN) ? W[(size_t)g * GIN + k] : 0.f;
}

__global__ void zero_ctx() {
    float4 z = {0.f, 0.f, 0.f, 0.f};
    for (size_t i = blockIdx.x * blockDim.x + threadIdx.x;
         i < (size_t)ML * H / 4; i += (size_t)gridDim.x * blockDim.x)
        ((float4*)d_ctx)[i] = z;
}

__global__ void zero_h0() {
    int i = blockIdx.x * blockDim.x + threadIdx.x;
    if (i < 2 * B * HD) d_h[i] = 0.f;
}

__global__ void prep_misc(const int* __restrict__ masks, const int* __restrict__ lens) {
    const int b = threadIdx.x;
    if (b >= B) return;
    int begin = 0, tnum = 0; bool found = false;
    for (int j = 0; j < L; j++) {
        int m = masks[b * L + j];
        tnum += m;
        if (!found && m == 1) { begin = j; found = true; }
    }
    const int len = lens[b];
    const float lf = (float)len;
    for (int j = 0; j < L; j++) {
        float w = (j < begin) ? (1.f - (float)(begin - j) / lf) : 0.f;
        if (masks[b * L + j] == 1) w = 1.f;
        if (j > begin + tnum) w = 1.f - (float)(j - begin) / lf;
        if (j > len) w = 0.f;
        d_wtab[b * L + j] = w;
    }
}

__global__ void prep_tbeff(const float* __restrict__ hb, const float* __restrict__ tW,
                           const float* __restrict__ tb) {
    const int i = threadIdx.x;
    if (i < NK * T) {
        const int kb = i >> 2;
        float s = tb[i];
        for (int r = 0; r < R; r++) s += hb[kb * R + r] * tW[i * R + r];
        d_tbeff[i] = s;
    }
}

// ---- GEMM 1: gi[dir][l*B+b][g] = x[b*L+l] @ Wp[dir]^T + bih ----
__global__ void __launch_bounds__(256) gemm_gi(const float* __restrict__ bihf,
                                               const float* __restrict__ bihb) {
    __shared__ __align__(16) float a_s[8][128];
    __shared__ __align__(16) float b_s[8][128];
    const int tid = threadIdx.x;
    const int n0 = blockIdx.x * 128;
    const int by = blockIdx.y;            // l
    const int dir = blockIdx.z;
    const float* Wp = d_Wp + (size_t)dir * G3 * GINP;

    const int ar = tid >> 1;              // 0..127
    const int ac = (tid & 1) * 4;         // 0 or 4
    const int tx = tid & 15, ty = tid >> 4;

    const float* arow = d_x + ((size_t)ar * 128 + by) * GINP + ac;
    const float* brow = Wp + (size_t)(n0 + ar) * GINP + ac;

    float acc[8][8];
#pragma unroll
    for (int i = 0; i < 8; i++)
#pragma unroll
        for (int j = 0; j < 8; j++) acc[i][j] = 0.f;

    for (int k0 = 0; k0 < GINP; k0 += 8) {
        float4 av = *(const float4*)(arow + k0);
        float4 bv = *(const float4*)(brow + k0);
        a_s[ac + 0][ar] = av.x; a_s[ac + 1][ar] = av.y;
        a_s[ac + 2][ar] = av.z; a_s[ac + 3][ar] = av.w;
        b_s[ac + 0][ar] = bv.x; b_s[ac + 1][ar] = bv.y;
        b_s[ac + 2][ar] = bv.z; b_s[ac + 3][ar] = bv.w;
        __syncthreads();
#pragma unroll
        for (int kk = 0; kk < 8; kk++) {
            float4 a0 = *(const float4*)&a_s[kk][ty * 8];
            float4 a1 = *(const float4*)&a_s[kk][ty * 8 + 4];
            float4 b0 = *(const float4*)&b_s[kk][tx * 8];
            float4 b1 = *(const float4*)&b_s[kk][tx * 8 + 4];
            float arr[8] = {a0.x, a0.y, a0.z, a0.w, a1.x, a1.y, a1.z, a1.w};
            float brr[8] = {b0.x, b0.y, b0.z, b0.w, b1.x, b1.y, b1.z, b1.w};
#pragma unroll
            for (int i = 0; i < 8; i++)
#pragma unroll
                for (int j = 0; j < 8; j++) acc[i][j] += arr[i] * brr[j];
        }
        __syncthreads();
    }
    const float* bih = dir ? bihb : bihf;
    float* C = d_gi + (size_t)dir * ML * G3;
#pragma unroll
    for (int i = 0; i < 8; i++) {
        size_t m = (size_t)by * 128 + ty * 8 + i;
        float* crow = C + m * G3 + n0 + tx * 8;
#pragma unroll
        for (int j = 0; j < 8; j++) crow[j] = acc[i][j] + bih[n0 + tx * 8 + j];
    }
}

// ---- GRU step: one launch per timestep. 128 blocks = 2 dirs x 64 unit-groups ----
__global__ void __launch_bounds__(128) gru_step(int t, const int* __restrict__ lens,
                                                const float* __restrict__ Whhf,
                                                const float* __restrict__ Whhb,
                                                const float* __restrict__ bhhf,
                                                const float* __restrict__ bhhb) {
    __shared__ __align__(16) float h_s[128][36];
    __shared__ __align__(16) float w_s[12][36];
    const int tid = threadIdx.x;
    const int dir = blockIdx.x >> 6;
    const int u0  = (blockIdx.x & 63) * 4;
    const float* Whh = dir ? Whhb : Whhf;
    const float* bhh = dir ? bhhb : bhhf;
    const int buf = t & 1;
    const float* hbase = d_h + buf * (2 * B * HD) + dir * (B * HD);
    float* hout = d_h + (buf ^ 1) * (2 * B * HD) + dir * (B * HD);

    const int u = tid >> 5;               // unit 0..3
    const int b0 = tid & 31;              // batch base
    float accR[4] = {0,0,0,0}, accZ[4] = {0,0,0,0}, accN[4] = {0,0,0,0};

    for (int k0 = 0; k0 < HD; k0 += 32) {
        for (int q = tid; q < 1024; q += 128) {
            int bb = q >> 3, jj = q & 7;
            *(float4*)&h_s[bb][jj * 4] = *(const float4*)(hbase + (size_t)bb * HD + k0 + jj * 4);
        }
        if (tid < 96) {
            int rr = tid >> 3, jj = tid & 7;
            *(float4*)&w_s[rr][jj * 4] =
                *(const float4*)(Whh + (size_t)((rr >> 2) * HD + u0 + (rr & 3)) * HD + k0 + jj * 4);
        }
        __syncthreads();
#pragma unroll
        for (int kk = 0; kk < 32; kk += 4) {
            float4 wr = *(const float4*)&w_s[u][kk];
            float4 wz = *(const float4*)&w_s[4 + u][kk];
            float4 wn = *(const float4*)&w_s[8 + u][kk];
#pragma unroll
            for (int s = 0; s < 4; s++) {
                float4 hv = *(const float4*)&h_s[b0 + 32 * s][kk];
                accR[s] += hv.x * wr.x + hv.y * wr.y + hv.z * wr.z + hv.w * wr.w;
                accZ[s] += hv.x * wz.x + hv.y * wz.y + hv.z * wz.z + hv.w * wz.w;
                accN[s] += hv.x * wn.x + hv.y * wn.y + hv.z * wn.z + hv.w * wn.w;
            }
        }
        __syncthreads();
    }

    const int ug = u0 + u;
    const float* gi = d_gi + (size_t)dir * ML * G3;
#pragma unroll
    for (int s = 0; s < 4; s++) {
        const int b = b0 + 32 * s;
        const int len = lens[b];
        const float hprev = hbase[(size_t)b * HD + ug];
        float hnext = hprev;
        if (t < len) {
            const int pos = dir ? (len - 1 - t) : t;
            const float* gp = gi + ((size_t)pos * B + b) * G3;
            const float rr = sigm(gp[ug] + accR[s] + bhh[ug]);
            const float zz = sigm(gp[256 + ug] + accZ[s] + bhh[256 + ug]);
            const float nn = tanhf(gp[512 + ug] + rr * (accN[s] + bhh[512 + ug]));
            hnext = (1.f - zz) * nn + zz * hprev;
            d_ctx[((size_t)b * L + pos) * H + dir * HD + ug] = hnext * d_wtab[b * L + pos];
        }
        hout[(size_t)b * HD + ug] = hnext;
    }
}

// ---- GEMM 2 fused: fk[kb][m][tt] = (ctx @ hW[kb]^T) @ tW[kb]^T + tbeff ----
__global__ void __launch_bounds__(256) gemm_ck(const float* __restrict__ hW,
                                               const float* __restrict__ tW) {
    __shared__ __align__(16) float a_s[8][128];
    __shared__ __align__(16) float b_s[8][128];
    __shared__ float tW_s[T * R];
    __shared__ float red[128 * 64];
    const int tid = threadIdx.x;
    const int m0 = blockIdx.x * 128;
    const int kb = blockIdx.y;
    const float* Wk = hW + (size_t)kb * R * H;

    for (int q = tid; q < T * R; q += 256) tW_s[q] = tW[kb * T * R + q];

    const int ar = tid >> 1, ac = (tid & 1) * 4;
    const int tx = tid & 15, ty = tid >> 4;
    const float* arow = d_ctx + (size_t)(m0 + ar) * H + ac;
    const float* brow = Wk + (size_t)ar * H + ac;

    float acc[8][8];
#pragma unroll
    for (int i = 0; i < 8; i++)
#pragma unroll
        for (int j = 0; j < 8; j++) acc[i][j] = 0.f;

    for (int k0 = 0; k0 < H; k0 += 8) {
        float4 av = *(const float4*)(arow + k0);
        float4 bv = *(const float4*)(brow + k0);
        a_s[ac + 0][ar] = av.x; a_s[ac + 1][ar] = av.y;
        a_s[ac + 2][ar] = av.z; a_s[ac + 3][ar] = av.w;
        b_s[ac + 0][ar] = bv.x; b_s[ac + 1][ar] = bv.y;
        b_s[ac + 2][ar] = bv.z; b_s[ac + 3][ar] = bv.w;
        __syncthreads();
#pragma unroll
        for (int kk = 0; kk < 8; kk++) {
            float4 a0 = *(const float4*)&a_s[kk][ty * 8];
            float4 a1 = *(const float4*)&a_s[kk][ty * 8 + 4];
            float4 b0 = *(const float4*)&b_s[kk][tx * 8];
            float4 b1 = *(const float4*)&b_s[kk][tx * 8 + 4];
            float arr[8] = {a0.x, a0.y, a0.z, a0.w, a1.x, a1.y, a1.z, a1.w};
            float brr[8] = {b0.x, b0.y, b0.z, b0.w, b1.x, b1.y, b1.z, b1.w};
#pragma unroll
            for (int i = 0; i < 8; i++)
#pragma unroll
                for (int j = 0; j < 8; j++) acc[i][j] += arr[i] * brr[j];
        }
        __syncthreads();
    }
    // partial fk reduce: red[row][tt][tx]
#pragma unroll
    for (int i = 0; i < 8; i++) {
        const int row = ty * 8 + i;
#pragma unroll
        for (int tt = 0; tt < 4; tt++) {
            float p = 0.f;
#pragma unroll
            for (int j = 0; j < 8; j++) p += acc[i][j] * tW_s[tt * R + tx * 8 + j];
            red[row * 64 + tt * 16 + tx] = p;
        }
    }
    __syncthreads();
    for (int idx = tid; idx < 512; idx += 256) {
        const int row = idx >> 2, tt = idx & 3;
        float s = d_tbeff[kb * T + tt];
#pragma unroll
        for (int x = 0; x < 16; x++) s += red[row * 64 + tt * 16 + x];
        d_fk[((size_t)kb * ML + m0 + row) * T + tt] = s;
    }
}

// ---- CRF forward-backward marginals ----
__global__ void __launch_bounds__(128) crf_kernel(const int* __restrict__ lens,
                                                  const float* __restrict__ trans) {
    const int tid = threadIdx.x;
    const int tag = tid & 3;
    const int chain = blockIdx.x * 32 + (tid >> 2);
    const int kb = chain >> 7;
    const int b  = chain & 127;
    const int len = lens[b];
    const unsigned fm = 0xffffffffu;
    const int base = (tid & 31) & ~3;

    float tcol[4], trow[4];
#pragma unroll
    for (int i = 0; i < 4; i++) {
        tcol[i] = trans[kb * 16 + i * 4 + tag];
        trow[i] = trans[kb * 16 + tag * 4 + i];
    }

    const float* f = d_fk + ((size_t)kb * ML + (size_t)b * L) * T;
    float* al = d_alpha + ((size_t)kb * ML + (size_t)b * L) * T;

    float alpha = f[tag];
    al[tag] = alpha;
    for (int l = 1; l < L; l++) {
        float a0 = __shfl_sync(fm, alpha, base + 0);
        float a1 = __shfl_sync(fm, alpha, base + 1);
        float a2 = __shfl_sync(fm, alpha, base + 2);
        float a3 = __shfl_sync(fm, alpha, base + 3);
        float na = lse4(a0 + tcol[0], a1 + tcol[1], a2 + tcol[2], a3 + tcol[3]) + f[l * T + tag];
        if (l < len) alpha = na;
        al[l * T + tag] = alpha;
    }

    float beta = 0.f, ssum = 0.f;
    float* sp = d_sp + (size_t)(kb * B + b) * L;
    for (int l = L - 1; l >= 0; l--) {
        float v = al[l * T + tag] + beta;
        float v0 = __shfl_sync(fm, v, base + 0);
        float v1 = __shfl_sync(fm, v, base + 1);
        float v2 = __shfl_sync(fm, v, base + 2);
        float v3 = __shfl_sync(fm, v, base + 3);
        float p1 = expf(v1 - lse4(v0, v1, v2, v3));
        float spl = (l < len) ? p1 : 0.f;
        ssum += spl;
        if (tag == 0) sp[l] = spl;
        if (l >= 1) {
            float fb = f[l * T + tag] + beta;
            float c0 = __shfl_sync(fm, fb, base + 0);
            float c1 = __shfl_sync(fm, fb, base + 1);
            float c2 = __shfl_sync(fm, fb, base + 2);
            float c3 = __shfl_sync(fm, fb, base + 3);
            float nb = lse4(trow[0] + c0, trow[1] + c1, trow[2] + c2, trow[3] + c3);
            if (l < len) beta = nb;
        }
    }
    if (tag == 0) d_spsum[kb * B + b] = ssum;
}

// ---- weighted pooling: sv[b][kb*H+h] = sum_l sp_norm * ctx ----
__global__ void __launch_bounds__(512) pool_kernel() {
    const int b = blockIdx.x, kb = blockIdx.y;
    __shared__ float sp_s[L];
    const int tid = threadIdx.x;
    const float inv = 1.f / d_spsum[kb * B + b];
    if (tid < L) sp_s[tid] = d_sp[(size_t)(kb * B + b) * L + tid] * inv;
    __syncthreads();
    float acc = 0.f;
    const float* c = d_ctx + (size_t)b * L * H + tid;
    for (int l = 0; l < L; l++) acc += sp_s[l] * c[(size_t)l * H];
    d_sv[(size_t)b * (4 * H) + kb * H + tid] = acc;
}

// ---- classifier scores ----
__global__ void __launch_bounds__(256) cls_kernel(const float* __restrict__ lW,
                                                  const float* __restrict__ lb) {
    const int b = blockIdx.x;
    const int tid = threadIdx.x;
    __shared__ float red[3][256];
    float p0 = 0.f, p1 = 0.f, p2 = 0.f;
    for (int h = tid; h < 4 * H; h += 256) {
        float s = fmaxf(d_sv[(size_t)b * 4 * H + h], 0.f);
        p0 += s * lW[h];
        p1 += s * lW[2048 + h];
        p2 += s * lW[4096 + h];
    }
    red[0][tid] = p0; red[1][tid] = p1; red[2][tid] = p2;
    __syncthreads();
    for (int off = 128; off > 0; off >>= 1) {
        if (tid < off) {
            red[0][tid] += red[0][tid + off];
            red[1][tid] += red[1][tid + off];
            red[2][tid] += red[2][tid + off];
        }
        __syncthreads();
    }
    if (tid < 3) d_scores[b * 3 + tid] = red[tid][0] + lb[tid];
}

__global__ void __launch_bounds__(128) loss_kernel(const int* __restrict__ labels,
                                                   float* __restrict__ out) {
    __shared__ float red[128];
    const int b = threadIdx.x;
    float s0 = d_scores[b * 3], s1 = d_scores[b * 3 + 1], s2 = d_scores[b * 3 + 2];
    float m = fmaxf(s0, fmaxf(s1, s2));
    float lse = m + logf(expf(s0 - m) + expf(s1 - m) + expf(s2 - m));
    int lab = labels[b];
    float sl = (lab == 0) ? s0 : ((lab == 1) ? s1 : s2);
    red[b] = lse - sl;
    __syncthreads();
    for (int off = 64; off > 0; off >>= 1) {
        if (b < off) red[b] += red[b + off];
        __syncthreads();
    }
    if (b == 0) out[0] = red[0] / (float)B;
}

extern "C" void kernel_launch(void* const* d_in, const int* in_sizes, int n_in,
                              void* d_out, int out_size) {
    (void)in_sizes; (void)n_in; (void)out_size;
    const float* sents = (const float*)d_in[0];
    const float* mtab  = (const float*)d_in[1];
    const float* gWihf = (const float*)d_in[2];
    const float* gWhhf = (const float*)d_in[3];
    const float* gbihf = (const float*)d_in[4];
    const float* gbhhf = (const float*)d_in[5];
    const float* gWihb = (const float*)d_in[6];
    const float* gWhhb = (const float*)d_in[7];
    const float* gbihb = (const float*)d_in[8];
    const float* gbhhb = (const float*)d_in[9];
    const float* hW    = (const float*)d_in[10];
    const float* hb    = (const float*)d_in[11];
    const float* tW    = (const float*)d_in[12];
    const float* tb    = (const float*)d_in[13];
    const float* trans = (const float*)d_in[14];
    const float* lW    = (const float*)d_in[15];
    const float* lb    = (const float*)d_in[16];
    const int* masks   = (const int*)d_in[17];
    const int* lens    = (const int*)d_in[18];
    const int* labels  = (const int*)d_in[19];
    float* out = (float*)d_out;

    prep_x<<<ML, 128>>>(sents, mtab, masks);
    prep_W<<<dim3(G3, 2), 128>>>(gWihf, gWihb);
    zero_ctx<<<2048, 256>>>();
    zero_h0<<<256, 256>>>();
    prep_misc<<<1, 128>>>(masks, lens);
    prep_tbeff<<<1, 32>>>(hb, tW, tb);
    gemm_gi<<<dim3(6, 128, 2), 256>>>(gbihf, gbihb);
    for (int t = 0; t < L; t++)
        gru_step<<<128, 128>>>(t, lens, gWhhf, gWhhb, gbhhf, gbhhb);
    gemm_ck<<<dim3(128, 4), 256>>>(hW, tW);
    crf_kernel<<<16, 128>>>(lens, trans);
    pool_kernel<<<dim3(B, NK), 512>>>();
    cls_kernel<<<B, 256>>>(lW, lb);
    loss_kernel<<<1, 128>>>(labels, out);
}

// round 3
// speedup vs baseline: 1.1319x; 1.1319x over previous
#include <cuda_runtime.h>
#include <math.h>
#include <stdint.h>

constexpr int B   = 128;
constexpr int L   = 128;
constexpr int D   = 300;
constexpr int MD  = 50;
constexpr int GIN = 350;
constexpr int GINP= 352;
constexpr int HD  = 256;
constexpr int G3  = 768;
constexpr int H   = 512;
constexpr int R   = 128;
constexpr int T   = 4;
constexpr int NK  = 4;
constexpr int ML  = B * L;

// ---- static scratch ----
__device__ float d_x[ML * GINP];
__device__ float d_Wp[2 * G3 * GINP];
__device__ float d_gi[2 * (size_t)ML * G3];
__device__ float d_h[2 * 2 * B * HD];
__device__ float d_ctx[(size_t)ML * H];
__device__ float d_wtab[ML];
__device__ float d_Wc[16 * H];
__device__ float d_fk[NK * ML * T];
__device__ float d_alpha[NK * ML * T];
__device__ float d_sp[NK * ML];
__device__ float d_spsum[NK * B];
__device__ float d_sv[NK * B * H];
__device__ float d_tbeff[NK * T];
__device__ float d_scores[B * 3];

__device__ __forceinline__ float sigm(float x) { return 1.f / (1.f + expf(-x)); }
__device__ __forceinline__ float lse4(float v0, float v1, float v2, float v3) {
    float mx = fmaxf(fmaxf(v0, v1), fmaxf(v2, v3));
    return mx + logf(expf(v0 - mx) + expf(v1 - mx) + expf(v2 - mx) + expf(v3 - mx));
}
__device__ __forceinline__ float tf32r(float x) {
    uint32_t u; asm("cvt.rna.tf32.f32 %0, %1;" : "=r"(u) : "f"(x));
    return __uint_as_float(u);
}
__device__ __forceinline__ void mma8(float* c, const uint32_t* a, const uint32_t* b) {
    asm("mma.sync.aligned.m16n8k8.row.col.f32.tf32.tf32.f32 "
        "{%0,%1,%2,%3},{%4,%5,%6,%7},{%8,%9},{%0,%1,%2,%3};"
        : "+f"(c[0]), "+f"(c[1]), "+f"(c[2]), "+f"(c[3])
        : "r"(a[0]), "r"(a[1]), "r"(a[2]), "r"(a[3]), "r"(b[0]), "r"(b[1]));
}

// ---- prep ----
__global__ void prep_x(const float* __restrict__ sents, const float* __restrict__ mtab,
                       const int* __restrict__ masks) {
    const int row = blockIdx.x;
    const int msk = masks[row];
    for (int k = threadIdx.x; k < GINP; k += blockDim.x) {
        float v;
        if (k < D)        v = sents[(size_t)row * D + k];
        else if (k < GIN) v = mtab[msk * MD + (k - D)];
        else              v = 0.f;
        d_x[(size_t)row * GINP + k] = v;
    }
}

__global__ void prep_W(const float* __restrict__ Wf, const float* __restrict__ Wb) {
    const int g = blockIdx.x, dd = blockIdx.y;
    const float* W = dd ? Wb : Wf;
    for (int k = threadIdx.x; k < GINP; k += blockDim.x)
        d_Wp[((size_t)dd * G3 + g) * GINP + k] = (k < GIN) ? W[(size_t)g * GIN + k] : 0.f;
}

__global__ void zero_ctx() {
    float4 z = {0.f, 0.f, 0.f, 0.f};
    for (size_t i = blockIdx.x * blockDim.x + threadIdx.x;
         i < (size_t)ML * H / 4; i += (size_t)gridDim.x * blockDim.x)
        ((float4*)d_ctx)[i] = z;
}

__global__ void zero_h0() {
    int i = blockIdx.x * blockDim.x + threadIdx.x;
    if (i < 2 * B * HD) d_h[i] = 0.f;
}

__global__ void prep_misc(const int* __restrict__ masks, const int* __restrict__ lens) {
    const int b = threadIdx.x;
    if (b >= B) return;
    int begin = 0, tnum = 0; bool found = false;
    for (int j = 0; j < L; j++) {
        int m = masks[b * L + j];
        tnum += m;
        if (!found && m == 1) { begin = j; found = true; }
    }
    const int len = lens[b];
    const float lf = (float)len;
    for (int j = 0; j < L; j++) {
        float w = (j < begin) ? (1.f - (float)(begin - j) / lf) : 0.f;
        if (masks[b * L + j] == 1) w = 1.f;
        if (j > begin + tnum) w = 1.f - (float)(j - begin) / lf;
        if (j > len) w = 0.f;
        d_wtab[b * L + j] = w;
    }
}

__global__ void prep_tbeff(const float* __restrict__ hb, const float* __restrict__ tW,
                           const float* __restrict__ tb) {
    const int i = threadIdx.x;
    if (i < NK * T) {
        const int kb = i >> 2;
        float s = tb[i];
        for (int r = 0; r < R; r++) s += hb[kb * R + r] * tW[i * R + r];
        d_tbeff[i] = s;
    }
}

// Wc[o=kb*4+tt][h] = sum_r tW[kb][tt][r] * hW[kb][r][h]
__global__ void prep_Wc(const float* __restrict__ hW, const float* __restrict__ tW) {
    const int idx = blockIdx.x * 256 + threadIdx.x;   // 8192
    const int kb = idx >> 11, tt = (idx >> 9) & 3, h = idx & 511;
    float s = 0.f;
    for (int r = 0; r < R; r++)
        s += tW[(kb * T + tt) * R + r] * hW[((size_t)kb * R + r) * H + h];
    d_Wc[idx] = s;
}

// ---- GEMM 1 (tf32 tensor cores): gi[dir][l*B+b][g] = x[b,l] @ Wp[dir]^T + bih ----
__global__ void __launch_bounds__(128) gemm_gi_tf32(const float* __restrict__ bihf,
                                                    const float* __restrict__ bihb) {
    __shared__ __align__(16) float a_s[128 * 20];
    __shared__ __align__(16) float b_s[128 * 20];
    const int tid = threadIdx.x;
    const int lane = tid & 31, warp = tid >> 5;
    const int n0 = blockIdx.x * 128;
    const int l  = blockIdx.y;
    const int dir = blockIdx.z;
    const int wm = (warp & 1) * 64, wn = (warp >> 1) * 64;
    const int lrow = tid >> 2, lc4 = (tid & 3) * 4;

    float acc[4][8][4];
#pragma unroll
    for (int i = 0; i < 4; i++)
#pragma unroll
        for (int j = 0; j < 8; j++)
#pragma unroll
            for (int q = 0; q < 4; q++) acc[i][j][q] = 0.f;

    for (int k0 = 0; k0 < GINP; k0 += 16) {
#pragma unroll
        for (int p = 0; p < 4; p++) {
            const int r = p * 32 + lrow;
            float4 va = *(const float4*)(d_x + ((size_t)r * L + l) * GINP + k0 + lc4);
            float4 vb = *(const float4*)(d_Wp + ((size_t)dir * G3 + n0 + r) * GINP + k0 + lc4);
            va.x = tf32r(va.x); va.y = tf32r(va.y); va.z = tf32r(va.z); va.w = tf32r(va.w);
            vb.x = tf32r(vb.x); vb.y = tf32r(vb.y); vb.z = tf32r(vb.z); vb.w = tf32r(vb.w);
            *(float4*)&a_s[r * 20 + lc4] = va;
            *(float4*)&b_s[r * 20 + lc4] = vb;
        }
        __syncthreads();
#pragma unroll
        for (int ks = 0; ks < 16; ks += 8) {
            uint32_t af[4][4], bf[8][2];
#pragma unroll
            for (int i = 0; i < 4; i++) {
                const int r0 = wm + i * 16 + (lane >> 2), cc = ks + (lane & 3);
                af[i][0] = __float_as_uint(a_s[r0 * 20 + cc]);
                af[i][1] = __float_as_uint(a_s[(r0 + 8) * 20 + cc]);
                af[i][2] = __float_as_uint(a_s[r0 * 20 + cc + 4]);
                af[i][3] = __float_as_uint(a_s[(r0 + 8) * 20 + cc + 4]);
            }
#pragma unroll
            for (int j = 0; j < 8; j++) {
                const int nn = wn + j * 8 + (lane >> 2), kk = ks + (lane & 3);
                bf[j][0] = __float_as_uint(b_s[nn * 20 + kk]);
                bf[j][1] = __float_as_uint(b_s[nn * 20 + kk + 4]);
            }
#pragma unroll
            for (int i = 0; i < 4; i++)
#pragma unroll
                for (int j = 0; j < 8; j++) mma8(acc[i][j], af[i], bf[j]);
        }
        __syncthreads();
    }
    const float* bih = dir ? bihb : bihf;
    float* C = d_gi + (size_t)dir * ML * G3 + (size_t)l * B * G3;
#pragma unroll
    for (int i = 0; i < 4; i++) {
        const int rb = wm + i * 16 + (lane >> 2);
#pragma unroll
        for (int j = 0; j < 8; j++) {
            const int nn = n0 + wn + j * 8 + 2 * (lane & 3);
            const float b0 = bih[nn], b1 = bih[nn + 1];
            float2 v0 = {acc[i][j][0] + b0, acc[i][j][1] + b1};
            float2 v1 = {acc[i][j][2] + b0, acc[i][j][3] + b1};
            *(float2*)(C + (size_t)rb * G3 + nn) = v0;
            *(float2*)(C + (size_t)(rb + 8) * G3 + nn) = v1;
        }
    }
}

// ---- GRU step: one launch per timestep ----
__global__ void __launch_bounds__(128) gru_step(int t, const int* __restrict__ lens,
                                                const float* __restrict__ Whhf,
                                                const float* __restrict__ Whhb,
                                                const float* __restrict__ bhhf,
                                                const float* __restrict__ bhhb) {
    __shared__ __align__(16) float h_s[128][36];
    __shared__ __align__(16) float w_s[12][36];
    const int tid = threadIdx.x;
    const int dir = blockIdx.x >> 6;
    const int u0  = (blockIdx.x & 63) * 4;
    const float* Whh = dir ? Whhb : Whhf;
    const float* bhh = dir ? bhhb : bhhf;
    const int buf = t & 1;
    const float* hbase = d_h + buf * (2 * B * HD) + dir * (B * HD);
    float* hout = d_h + (buf ^ 1) * (2 * B * HD) + dir * (B * HD);

    const int u = tid >> 5;
    const int b0 = tid & 31;
    float accR[4] = {0,0,0,0}, accZ[4] = {0,0,0,0}, accN[4] = {0,0,0,0};

    for (int k0 = 0; k0 < HD; k0 += 32) {
        for (int q = tid; q < 1024; q += 128) {
            int bb = q >> 3, jj = q & 7;
            *(float4*)&h_s[bb][jj * 4] = *(const float4*)(hbase + (size_t)bb * HD + k0 + jj * 4);
        }
        if (tid < 96) {
            int rr = tid >> 3, jj = tid & 7;
            *(float4*)&w_s[rr][jj * 4] =
                *(const float4*)(Whh + (size_t)((rr >> 2) * HD + u0 + (rr & 3)) * HD + k0 + jj * 4);
        }
        __syncthreads();
#pragma unroll
        for (int kk = 0; kk < 32; kk += 4) {
            float4 wr = *(const float4*)&w_s[u][kk];
            float4 wz = *(const float4*)&w_s[4 + u][kk];
            float4 wn = *(const float4*)&w_s[8 + u][kk];
#pragma unroll
            for (int s = 0; s < 4; s++) {
                float4 hv = *(const float4*)&h_s[b0 + 32 * s][kk];
                accR[s] += hv.x * wr.x + hv.y * wr.y + hv.z * wr.z + hv.w * wr.w;
                accZ[s] += hv.x * wz.x + hv.y * wz.y + hv.z * wz.z + hv.w * wz.w;
                accN[s] += hv.x * wn.x + hv.y * wn.y + hv.z * wn.z + hv.w * wn.w;
            }
        }
        __syncthreads();
    }

    const int ug = u0 + u;
    const float* gi = d_gi + (size_t)dir * ML * G3;
#pragma unroll
    for (int s = 0; s < 4; s++) {
        const int b = b0 + 32 * s;
        const int len = lens[b];
        const float hprev = hbase[(size_t)b * HD + ug];
        float hnext = hprev;
        if (t < len) {
            const int pos = dir ? (len - 1 - t) : t;
            const float* gp = gi + ((size_t)pos * B + b) * G3;
            const float rr = sigm(gp[ug] + accR[s] + bhh[ug]);
            const float zz = sigm(gp[256 + ug] + accZ[s] + bhh[256 + ug]);
            const float nn = tanhf(gp[512 + ug] + rr * (accN[s] + bhh[512 + ug]));
            hnext = (1.f - zz) * nn + zz * hprev;
            d_ctx[((size_t)b * L + pos) * H + dir * HD + ug] = hnext * d_wtab[b * L + pos];
        }
        hout[(size_t)b * HD + ug] = hnext;
    }
}

// ---- fk = ctx @ Wc^T + tbeff  (skinny GEMM, one thread per (m, o)) ----
__global__ void __launch_bounds__(256) fk_kernel() {
    const int idx = blockIdx.x * 256 + threadIdx.x;  // 262144
    const int m = idx >> 4, o = idx & 15;
    const float4* cx = (const float4*)(d_ctx + (size_t)m * H);
    const float4* w  = (const float4*)(d_Wc + (size_t)o * H);
    float s = d_tbeff[o];
#pragma unroll 4
    for (int k = 0; k < H / 4; k++) {
        float4 c = cx[k], ww = w[k];
        s += c.x * ww.x + c.y * ww.y + c.z * ww.z + c.w * ww.w;
    }
    d_fk[((size_t)(o >> 2) * ML + m) * T + (o & 3)] = s;
}

// ---- CRF forward-backward marginals ----
__global__ void __launch_bounds__(128) crf_kernel(const int* __restrict__ lens,
                                                  const float* __restrict__ trans) {
    const int tid = threadIdx.x;
    const int tag = tid & 3;
    const int chain = blockIdx.x * 32 + (tid >> 2);
    const int kb = chain >> 7;
    const int b  = chain & 127;
    const int len = lens[b];
    const unsigned fm = 0xffffffffu;
    const int base = (tid & 31) & ~3;

    float tcol[4], trow[4];
#pragma unroll
    for (int i = 0; i < 4; i++) {
        tcol[i] = trans[kb * 16 + i * 4 + tag];
        trow[i] = trans[kb * 16 + tag * 4 + i];
    }

    const float* f = d_fk + ((size_t)kb * ML + (size_t)b * L) * T;
    float* al = d_alpha + ((size_t)kb * ML + (size_t)b * L) * T;

    float alpha = f[tag];
    al[tag] = alpha;
    for (int l = 1; l < L; l++) {
        float a0 = __shfl_sync(fm, alpha, base + 0);
        float a1 = __shfl_sync(fm, alpha, base + 1);
        float a2 = __shfl_sync(fm, alpha, base + 2);
        float a3 = __shfl_sync(fm, alpha, base + 3);
        float na = lse4(a0 + tcol[0], a1 + tcol[1], a2 + tcol[2], a3 + tcol[3]) + f[l * T + tag];
        if (l < len) alpha = na;
        al[l * T + tag] = alpha;
    }

    float beta = 0.f, ssum = 0.f;
    float* sp = d_sp + (size_t)(kb * B + b) * L;
    for (int l = L - 1; l >= 0; l--) {
        float v = al[l * T + tag] + beta;
        float v0 = __shfl_sync(fm, v, base + 0);
        float v1 = __shfl_sync(fm, v, base + 1);
        float v2 = __shfl_sync(fm, v, base + 2);
        float v3 = __shfl_sync(fm, v, base + 3);
        float p1 = expf(v1 - lse4(v0, v1, v2, v3));
        float spl = (l < len) ? p1 : 0.f;
        ssum += spl;
        if (tag == 0) sp[l] = spl;
        if (l >= 1) {
            float fb = f[l * T + tag] + beta;
            float c0 = __shfl_sync(fm, fb, base + 0);
            float c1 = __shfl_sync(fm, fb, base + 1);
            float c2 = __shfl_sync(fm, fb, base + 2);
            float c3 = __shfl_sync(fm, fb, base + 3);
            float nb = lse4(trow[0] + c0, trow[1] + c1, trow[2] + c2, trow[3] + c3);
            if (l < len) beta = nb;
        }
    }
    if (tag == 0) d_spsum[kb * B + b] = ssum;
}

// ---- weighted pooling ----
__global__ void __launch_bounds__(512) pool_kernel() {
    const int b = blockIdx.x, kb = blockIdx.y;
    __shared__ float sp_s[L];
    const int tid = threadIdx.x;
    const float inv = 1.f / d_spsum[kb * B + b];
    if (tid < L) sp_s[tid] = d_sp[(size_t)(kb * B + b) * L + tid] * inv;
    __syncthreads();
    float acc = 0.f;
    const float* c = d_ctx + (size_t)b * L * H + tid;
    for (int l = 0; l < L; l++) acc += sp_s[l] * c[(size_t)l * H];
    d_sv[(size_t)b * (4 * H) + kb * H + tid] = acc;
}

// ---- classifier ----
__global__ void __launch_bounds__(256) cls_kernel(const float* __restrict__ lW,
                                                  const float* __restrict__ lb) {
    const int b = blockIdx.x;
    const int tid = threadIdx.x;
    __shared__ float red[3][256];
    float p0 = 0.f, p1 = 0.f, p2 = 0.f;
    for (int h = tid; h < 4 * H; h += 256) {
        float s = fmaxf(d_sv[(size_t)b * 4 * H + h], 0.f);
        p0 += s * lW[h];
        p1 += s * lW[2048 + h];
        p2 += s * lW[4096 + h];
    }
    red[0][tid] = p0; red[1][tid] = p1; red[2][tid] = p2;
    __syncthreads();
    for (int off = 128; off > 0; off >>= 1) {
        if (tid < off) {
            red[0][tid] += red[0][tid + off];
            red[1][tid] += red[1][tid + off];
            red[2][tid] += red[2][tid + off];
        }
        __syncthreads();
    }
    if (tid < 3) d_scores[b * 3 + tid] = red[tid][0] + lb[tid];
}

__global__ void __launch_bounds__(128) loss_kernel(const int* __restrict__ labels,
                                                   float* __restrict__ out) {
    __shared__ float red[128];
    const int b = threadIdx.x;
    float s0 = d_scores[b * 3], s1 = d_scores[b * 3 + 1], s2 = d_scores[b * 3 + 2];
    float m = fmaxf(s0, fmaxf(s1, s2));
    float lse = m + logf(expf(s0 - m) + expf(s1 - m) + expf(s2 - m));
    int lab = labels[b];
    float sl = (lab == 0) ? s0 : ((lab == 1) ? s1 : s2);
    red[b] = lse - sl;
    __syncthreads();
    for (int off = 64; off > 0; off >>= 1) {
        if (b < off) red[b] += red[b + off];
        __syncthreads();
    }
    if (b == 0) out[0] = red[0] / (float)B;
}

extern "C" void kernel_launch(void* const* d_in, const int* in_sizes, int n_in,
                              void* d_out, int out_size) {
    (void)in_sizes; (void)n_in; (void)out_size;
    const float* sents = (const float*)d_in[0];
    const float* mtab  = (const float*)d_in[1];
    const float* gWihf = (const float*)d_in[2];
    const float* gWhhf = (const float*)d_in[3];
    const float* gbihf = (const float*)d_in[4];
    const float* gbhhf = (const float*)d_in[5];
    const float* gWihb = (const float*)d_in[6];
    const float* gWhhb = (const float*)d_in[7];
    const float* gbihb = (const float*)d_in[8];
    const float* gbhhb = (const float*)d_in[9];
    const float* hW    = (const float*)d_in[10];
    const float* hb    = (const float*)d_in[11];
    const float* tW    = (const float*)d_in[12];
    const float* tb    = (const float*)d_in[13];
    const float* trans = (const float*)d_in[14];
    const float* lW    = (const float*)d_in[15];
    const float* lb    = (const float*)d_in[16];
    const int* masks   = (const int*)d_in[17];
    const int* lens    = (const int*)d_in[18];
    const int* labels  = (const int*)d_in[19];
    float* out = (float*)d_out;

    prep_x<<<ML, 128>>>(sents, mtab, masks);
    prep_W<<<dim3(G3, 2), 128>>>(gWihf, gWihb);
    zero_ctx<<<2048, 256>>>();
    gemm_gi_tf32<<<dim3(6, 128, 2), 128>>>(gbihf, gbihb);   // 4th launch -> ncu window
    zero_h0<<<256, 256>>>();
    prep_misc<<<1, 128>>>(masks, lens);
    prep_tbeff<<<1, 32>>>(hb, tW, tb);
    prep_Wc<<<32, 256>>>(hW, tW);
    for (int t = 0; t < L; t++)
        gru_step<<<128, 128>>>(t, lens, gWhhf, gWhhb, gbhhf, gbhhb);
    fk_kernel<<<1024, 256>>>();
    crf_kernel<<<16, 128>>>(lens, trans);
    pool_kernel<<<dim3(B, NK), 512>>>();
    cls_kernel<<<B, 256>>>(lW, lb);
    loss_kernel<<<1, 128>>>(labels, out);
}

// round 4
// speedup vs baseline: 1.2328x; 1.0891x over previous
#include <cuda_runtime.h>
#include <math.h>
#include <stdint.h>

constexpr int B   = 128;
constexpr int L   = 128;
constexpr int D   = 300;
constexpr int MD  = 50;
constexpr int GIN = 350;
constexpr int GINP= 352;
constexpr int HD  = 256;
constexpr int G3  = 768;
constexpr int H   = 512;
constexpr int R   = 128;
constexpr int T   = 4;
constexpr int NK  = 4;
constexpr int ML  = B * L;

// ---- static scratch ----
__device__ float d_x[ML * GINP];
__device__ float d_Wp[2 * G3 * GINP];
__device__ float d_gi[2 * (size_t)ML * G3];
__device__ float d_h[2 * 2 * B * HD];
__device__ float d_ctx[(size_t)ML * H];
__device__ float d_wtab[ML];
__device__ float d_Wc[16 * H];
__device__ float d_fk[NK * ML * T];
__device__ float d_alpha[NK * ML * T];
__device__ float d_sp[NK * ML];
__device__ float d_spsum[NK * B];
__device__ float d_sv[NK * B * H];
__device__ float d_tbeff[NK * T];
__device__ float d_scores[B * 3];
__device__ unsigned d_barcnt;
__device__ unsigned d_barflag;

__device__ __forceinline__ float sigm(float x) { return 1.f / (1.f + expf(-x)); }
__device__ __forceinline__ float lse4(float v0, float v1, float v2, float v3) {
    float mx = fmaxf(fmaxf(v0, v1), fmaxf(v2, v3));
    return mx + logf(expf(v0 - mx) + expf(v1 - mx) + expf(v2 - mx) + expf(v3 - mx));
}
__device__ __forceinline__ float tf32r(float x) {
    uint32_t u; asm("cvt.rna.tf32.f32 %0, %1;" : "=r"(u) : "f"(x));
    return __uint_as_float(u);
}
__device__ __forceinline__ void mma8(float* c, const uint32_t* a, const uint32_t* b) {
    asm("mma.sync.aligned.m16n8k8.row.col.f32.tf32.tf32.f32 "
        "{%0,%1,%2,%3},{%4,%5,%6,%7},{%8,%9},{%0,%1,%2,%3};"
        : "+f"(c[0]), "+f"(c[1]), "+f"(c[2]), "+f"(c[3])
        : "r"(a[0]), "r"(a[1]), "r"(a[2]), "r"(a[3]), "r"(b[0]), "r"(b[1]));
}

// ---- prep_all: x concat, W pad, pos-weights (fused into one launch) ----
__global__ void prep_all(const float* __restrict__ sents, const float* __restrict__ mtab,
                         const int* __restrict__ masks, const int* __restrict__ lens,
                         const float* __restrict__ Wf, const float* __restrict__ Wb) {
    const int bid = blockIdx.x;
    if (bid < ML) {
        const int row = bid;
        const int msk = masks[row];
        for (int k = threadIdx.x; k < GINP; k += blockDim.x) {
            float v;
            if (k < D)        v = sents[(size_t)row * D + k];
            else if (k < GIN) v = mtab[msk * MD + (k - D)];
            else              v = 0.f;
            d_x[(size_t)row * GINP + k] = v;
        }
    } else if (bid < ML + 2 * G3) {
        const int q = bid - ML;
        const int dd = q / G3, g = q % G3;
        const float* W = dd ? Wb : Wf;
        for (int k = threadIdx.x; k < GINP; k += blockDim.x)
            d_Wp[((size_t)dd * G3 + g) * GINP + k] = (k < GIN) ? W[(size_t)g * GIN + k] : 0.f;
    } else {
        const int b = threadIdx.x;
        if (b >= B) return;
        int begin = 0, tnum = 0; bool found = false;
        for (int j = 0; j < L; j++) {
            int m = masks[b * L + j];
            tnum += m;
            if (!found && m == 1) { begin = j; found = true; }
        }
        const int len = lens[b];
        const float lf = (float)len;
        for (int j = 0; j < L; j++) {
            float w = (j < begin) ? (1.f - (float)(begin - j) / lf) : 0.f;
            if (masks[b * L + j] == 1) w = 1.f;
            if (j > begin + tnum) w = 1.f - (float)(j - begin) / lf;
            if (j > len) w = 0.f;
            d_wtab[b * L + j] = w;
        }
    }
}

// ---- zero_all: ctx, h buf0, barrier state ----
__global__ void zero_all() {
    float4 z = {0.f, 0.f, 0.f, 0.f};
    const size_t gid = (size_t)blockIdx.x * blockDim.x + threadIdx.x;
    for (size_t i = gid; i < (size_t)ML * H / 4; i += (size_t)gridDim.x * blockDim.x)
        ((float4*)d_ctx)[i] = z;
    if (gid < 2 * B * HD / 4) ((float4*)d_h)[gid] = z;
    if (gid == 0) { d_barcnt = 0; d_barflag = 0; }
}

// ---- GEMM 1 (tf32): gi[dir][l*B+b][g] = x[b,l] @ Wp[dir]^T + bih ----
__global__ void __launch_bounds__(128) gemm_gi_tf32(const float* __restrict__ bihf,
                                                    const float* __restrict__ bihb) {
    __shared__ __align__(16) float a_s[128 * 20];
    __shared__ __align__(16) float b_s[128 * 20];
    const int tid = threadIdx.x;
    const int lane = tid & 31, warp = tid >> 5;
    const int n0 = blockIdx.x * 128;
    const int l  = blockIdx.y;
    const int dir = blockIdx.z;
    const int wm = (warp & 1) * 64, wn = (warp >> 1) * 64;
    const int lrow = tid >> 2, lc4 = (tid & 3) * 4;

    float acc[4][8][4];
#pragma unroll
    for (int i = 0; i < 4; i++)
#pragma unroll
        for (int j = 0; j < 8; j++)
#pragma unroll
            for (int q = 0; q < 4; q++) acc[i][j][q] = 0.f;

    for (int k0 = 0; k0 < GINP; k0 += 16) {
#pragma unroll
        for (int p = 0; p < 4; p++) {
            const int r = p * 32 + lrow;
            float4 va = *(const float4*)(d_x + ((size_t)r * L + l) * GINP + k0 + lc4);
            float4 vb = *(const float4*)(d_Wp + ((size_t)dir * G3 + n0 + r) * GINP + k0 + lc4);
            va.x = tf32r(va.x); va.y = tf32r(va.y); va.z = tf32r(va.z); va.w = tf32r(va.w);
            vb.x = tf32r(vb.x); vb.y = tf32r(vb.y); vb.z = tf32r(vb.z); vb.w = tf32r(vb.w);
            *(float4*)&a_s[r * 20 + lc4] = va;
            *(float4*)&b_s[r * 20 + lc4] = vb;
        }
        __syncthreads();
#pragma unroll
        for (int ks = 0; ks < 16; ks += 8) {
            uint32_t af[4][4], bf[8][2];
#pragma unroll
            for (int i = 0; i < 4; i++) {
                const int r0 = wm + i * 16 + (lane >> 2), cc = ks + (lane & 3);
                af[i][0] = __float_as_uint(a_s[r0 * 20 + cc]);
                af[i][1] = __float_as_uint(a_s[(r0 + 8) * 20 + cc]);
                af[i][2] = __float_as_uint(a_s[r0 * 20 + cc + 4]);
                af[i][3] = __float_as_uint(a_s[(r0 + 8) * 20 + cc + 4]);
            }
#pragma unroll
            for (int j = 0; j < 8; j++) {
                const int nn = wn + j * 8 + (lane >> 2), kk = ks + (lane & 3);
                bf[j][0] = __float_as_uint(b_s[nn * 20 + kk]);
                bf[j][1] = __float_as_uint(b_s[nn * 20 + kk + 4]);
            }
#pragma unroll
            for (int i = 0; i < 4; i++)
#pragma unroll
                for (int j = 0; j < 8; j++) mma8(acc[i][j], af[i], bf[j]);
        }
        __syncthreads();
    }
    const float* bih = dir ? bihb : bihf;
    float* C = d_gi + (size_t)dir * ML * G3 + (size_t)l * B * G3;
#pragma unroll
    for (int i = 0; i < 4; i++) {
        const int rb = wm + i * 16 + (lane >> 2);
#pragma unroll
        for (int j = 0; j < 8; j++) {
            const int nn = n0 + wn + j * 8 + 2 * (lane & 3);
            const float b0 = bih[nn], b1 = bih[nn + 1];
            float2 v0 = {acc[i][j][0] + b0, acc[i][j][1] + b1};
            float2 v1 = {acc[i][j][2] + b0, acc[i][j][3] + b1};
            *(float2*)(C + (size_t)rb * G3 + nn) = v0;
            *(float2*)(C + (size_t)(rb + 8) * G3 + nn) = v1;
        }
    }
}

// ---- persistent GRU: all 128 timesteps in one kernel, grid barrier per step ----
__global__ void __launch_bounds__(256, 1) gru_persistent(const int* __restrict__ lens,
                                                         const float* __restrict__ Whhf,
                                                         const float* __restrict__ Whhb,
                                                         const float* __restrict__ bhhf,
                                                         const float* __restrict__ bhhb) {
    __shared__ __align__(16) float w_s[12 * 256];
    __shared__ __align__(16) float h_s[128][36];
    __shared__ int len_s[128];
    const int tid = threadIdx.x;
    const int dir = blockIdx.x >> 6;
    const int u0  = (blockIdx.x & 63) * 4;
    const float* Whh = dir ? Whhb : Whhf;
    const float* bhh = dir ? bhhb : bhhf;

    // load 12 weight rows (3 gates x 4 units) once
    for (int q = tid; q < 12 * 64; q += 256) {
        const int row = q >> 6, jj = q & 63;
        const int g = row >> 2, uu = row & 3;
        *(float4*)&w_s[row * 256 + jj * 4] =
            *(const float4*)(Whh + (size_t)(g * HD + u0 + uu) * HD + jj * 4);
    }
    if (tid < 128) len_s[tid] = lens[tid];
    __syncthreads();

    const int u = tid >> 6, b0 = tid & 63;
    const int ug = u0 + u;
    const float bR = bhh[ug], bZ = bhh[256 + ug], bN = bhh[512 + ug];
    const float* gi = d_gi + (size_t)dir * ML * G3;

    for (int t = 0; t < L; t++) {
        const int buf = t & 1;
        const float* hbase = d_h + buf * (2 * B * HD) + dir * (B * HD);
        float* hout = d_h + (buf ^ 1) * (2 * B * HD) + dir * (B * HD);

        float accR[2] = {0.f, 0.f}, accZ[2] = {0.f, 0.f}, accN[2] = {0.f, 0.f};
        for (int k0 = 0; k0 < HD; k0 += 32) {
            for (int q = tid; q < 1024; q += 256) {
                const int bb = q >> 3, jj = q & 7;
                *(float4*)&h_s[bb][jj * 4] = *(const float4*)(hbase + (size_t)bb * HD + k0 + jj * 4);
            }
            __syncthreads();
#pragma unroll
            for (int kk = 0; kk < 32; kk += 4) {
                float4 wr = *(const float4*)&w_s[u * 256 + k0 + kk];
                float4 wz = *(const float4*)&w_s[(4 + u) * 256 + k0 + kk];
                float4 wn = *(const float4*)&w_s[(8 + u) * 256 + k0 + kk];
#pragma unroll
                for (int s = 0; s < 2; s++) {
                    float4 hv = *(const float4*)&h_s[b0 + 64 * s][kk];
                    accR[s] += hv.x * wr.x + hv.y * wr.y + hv.z * wr.z + hv.w * wr.w;
                    accZ[s] += hv.x * wz.x + hv.y * wz.y + hv.z * wz.z + hv.w * wz.w;
                    accN[s] += hv.x * wn.x + hv.y * wn.y + hv.z * wn.z + hv.w * wn.w;
                }
            }
            __syncthreads();
        }

#pragma unroll
        for (int s = 0; s < 2; s++) {
            const int b = b0 + 64 * s;
            const int len = len_s[b];
            const float hprev = hbase[(size_t)b * HD + ug];
            float hnext = hprev;
            if (t < len) {
                const int pos = dir ? (len - 1 - t) : t;
                const float* gp = gi + ((size_t)pos * B + b) * G3;
                const float rr = sigm(gp[ug] + accR[s] + bR);
                const float zz = sigm(gp[256 + ug] + accZ[s] + bZ);
                const float nn = tanhf(gp[512 + ug] + rr * (accN[s] + bN));
                hnext = (1.f - zz) * nn + zz * hprev;
                d_ctx[((size_t)b * L + pos) * H + dir * HD + ug] = hnext * d_wtab[b * L + pos];
            }
            hout[(size_t)b * HD + ug] = hnext;
        }

        // ---- grid barrier ----
        __syncthreads();
        if (tid == 0) {
            __threadfence();
            const unsigned target = (unsigned)(t + 1);
            const unsigned arr = atomicAdd(&d_barcnt, 1u);
            if (arr == (unsigned)gridDim.x - 1u) {
                d_barcnt = 0u;
                __threadfence();
                atomicExch(&d_barflag, target);
            } else {
                while (*(volatile unsigned*)&d_barflag < target) { __nanosleep(64); }
            }
            __threadfence();
        }
        __syncthreads();
    }
}

__global__ void prep_tbeff(const float* __restrict__ hb, const float* __restrict__ tW,
                           const float* __restrict__ tb) {
    const int i = threadIdx.x;
    if (i < NK * T) {
        const int kb = i >> 2;
        float s = tb[i];
        for (int r = 0; r < R; r++) s += hb[kb * R + r] * tW[i * R + r];
        d_tbeff[i] = s;
    }
}

__global__ void prep_Wc(const float* __restrict__ hW, const float* __restrict__ tW) {
    const int idx = blockIdx.x * 256 + threadIdx.x;   // 8192
    const int kb = idx >> 11, tt = (idx >> 9) & 3, h = idx & 511;
    float s = 0.f;
    for (int r = 0; r < R; r++)
        s += tW[(kb * T + tt) * R + r] * hW[((size_t)kb * R + r) * H + h];
    d_Wc[idx] = s;
}

// ---- fk = ctx @ Wc^T + tbeff ----
__global__ void __launch_bounds__(256) fk_kernel() {
    const int idx = blockIdx.x * 256 + threadIdx.x;  // 262144
    const int m = idx >> 4, o = idx & 15;
    const float4* cx = (const float4*)(d_ctx + (size_t)m * H);
    const float4* w  = (const float4*)(d_Wc + (size_t)o * H);
    float s = d_tbeff[o];
#pragma unroll 4
    for (int k = 0; k < H / 4; k++) {
        float4 c = cx[k], ww = w[k];
        s += c.x * ww.x + c.y * ww.y + c.z * ww.z + c.w * ww.w;
    }
    d_fk[((size_t)(o >> 2) * ML + m) * T + (o & 3)] = s;
}

// ---- CRF forward-backward marginals ----
__global__ void __launch_bounds__(128) crf_kernel(const int* __restrict__ lens,
                                                  const float* __restrict__ trans) {
    const int tid = threadIdx.x;
    const int tag = tid & 3;
    const int chain = blockIdx.x * 32 + (tid >> 2);
    const int kb = chain >> 7;
    const int b  = chain & 127;
    const int len = lens[b];
    const unsigned fm = 0xffffffffu;
    const int base = (tid & 31) & ~3;

    float tcol[4], trow[4];
#pragma unroll
    for (int i = 0; i < 4; i++) {
        tcol[i] = trans[kb * 16 + i * 4 + tag];
        trow[i] = trans[kb * 16 + tag * 4 + i];
    }

    const float* f = d_fk + ((size_t)kb * ML + (size_t)b * L) * T;
    float* al = d_alpha + ((size_t)kb * ML + (size_t)b * L) * T;

    float alpha = f[tag];
    al[tag] = alpha;
    for (int l = 1; l < L; l++) {
        float a0 = __shfl_sync(fm, alpha, base + 0);
        float a1 = __shfl_sync(fm, alpha, base + 1);
        float a2 = __shfl_sync(fm, alpha, base + 2);
        float a3 = __shfl_sync(fm, alpha, base + 3);
        float na = lse4(a0 + tcol[0], a1 + tcol[1], a2 + tcol[2], a3 + tcol[3]) + f[l * T + tag];
        if (l < len) alpha = na;
        al[l * T + tag] = alpha;
    }

    float beta = 0.f, ssum = 0.f;
    float* sp = d_sp + (size_t)(kb * B + b) * L;
    for (int l = L - 1; l >= 0; l--) {
        float v = al[l * T + tag] + beta;
        float v0 = __shfl_sync(fm, v, base + 0);
        float v1 = __shfl_sync(fm, v, base + 1);
        float v2 = __shfl_sync(fm, v, base + 2);
        float v3 = __shfl_sync(fm, v, base + 3);
        float p1 = expf(v1 - lse4(v0, v1, v2, v3));
        float spl = (l < len) ? p1 : 0.f;
        ssum += spl;
        if (tag == 0) sp[l] = spl;
        if (l >= 1) {
            float fb = f[l * T + tag] + beta;
            float c0 = __shfl_sync(fm, fb, base + 0);
            float c1 = __shfl_sync(fm, fb, base + 1);
            float c2 = __shfl_sync(fm, fb, base + 2);
            float c3 = __shfl_sync(fm, fb, base + 3);
            float nb = lse4(trow[0] + c0, trow[1] + c1, trow[2] + c2, trow[3] + c3);
            if (l < len) beta = nb;
        }
    }
    if (tag == 0) d_spsum[kb * B + b] = ssum;
}

// ---- weighted pooling ----
__global__ void __launch_bounds__(512) pool_kernel() {
    const int b = blockIdx.x, kb = blockIdx.y;
    __shared__ float sp_s[L];
    const int tid = threadIdx.x;
    const float inv = 1.f / d_spsum[kb * B + b];
    if (tid < L) sp_s[tid] = d_sp[(size_t)(kb * B + b) * L + tid] * inv;
    __syncthreads();
    float acc = 0.f;
    const float* c = d_ctx + (size_t)b * L * H + tid;
    for (int l = 0; l < L; l++) acc += sp_s[l] * c[(size_t)l * H];
    d_sv[(size_t)b * (4 * H) + kb * H + tid] = acc;
}

// ---- classifier ----
__global__ void __launch_bounds__(256) cls_kernel(const float* __restrict__ lW,
                                                  const float* __restrict__ lb) {
    const int b = blockIdx.x;
    const int tid = threadIdx.x;
    __shared__ float red[3][256];
    float p0 = 0.f, p1 = 0.f, p2 = 0.f;
    for (int h = tid; h < 4 * H; h += 256) {
        float s = fmaxf(d_sv[(size_t)b * 4 * H + h], 0.f);
        p0 += s * lW[h];
        p1 += s * lW[2048 + h];
        p2 += s * lW[4096 + h];
    }
    red[0][tid] = p0; red[1][tid] = p1; red[2][tid] = p2;
    __syncthreads();
    for (int off = 128; off > 0; off >>= 1) {
        if (tid < off) {
            red[0][tid] += red[0][tid + off];
            red[1][tid] += red[1][tid + off];
            red[2][tid] += red[2][tid + off];
        }
        __syncthreads();
    }
    if (tid < 3) d_scores[b * 3 + tid] = red[tid][0] + lb[tid];
}

__global__ void __launch_bounds__(128) loss_kernel(const int* __restrict__ labels,
                                                   float* __restrict__ out) {
    __shared__ float red[128];
    const int b = threadIdx.x;
    float s0 = d_scores[b * 3], s1 = d_scores[b * 3 + 1], s2 = d_scores[b * 3 + 2];
    float m = fmaxf(s0, fmaxf(s1, s2));
    float lse = m + logf(expf(s0 - m) + expf(s1 - m) + expf(s2 - m));
    int lab = labels[b];
    float sl = (lab == 0) ? s0 : ((lab == 1) ? s1 : s2);
    red[b] = lse - sl;
    __syncthreads();
    for (int off = 64; off > 0; off >>= 1) {
        if (b < off) red[b] += red[b + off];
        __syncthreads();
    }
    if (b == 0) out[0] = red[0] / (float)B;
}

extern "C" void kernel_launch(void* const* d_in, const int* in_sizes, int n_in,
                              void* d_out, int out_size) {
    (void)in_sizes; (void)n_in; (void)out_size;
    const float* sents = (const float*)d_in[0];
    const float* mtab  = (const float*)d_in[1];
    const float* gWihf = (const float*)d_in[2];
    const float* gWhhf = (const float*)d_in[3];
    const float* gbihf = (const float*)d_in[4];
    const float* gbhhf = (const float*)d_in[5];
    const float* gWihb = (const float*)d_in[6];
    const float* gWhhb = (const float*)d_in[7];
    const float* gbihb = (const float*)d_in[8];
    const float* gbhhb = (const float*)d_in[9];
    const float* hW    = (const float*)d_in[10];
    const float* hb    = (const float*)d_in[11];
    const float* tW    = (const float*)d_in[12];
    const float* tb    = (const float*)d_in[13];
    const float* trans = (const float*)d_in[14];
    const float* lW    = (const float*)d_in[15];
    const float* lb    = (const float*)d_in[16];
    const int* masks   = (const int*)d_in[17];
    const int* lens    = (const int*)d_in[18];
    const int* labels  = (const int*)d_in[19];
    float* out = (float*)d_out;

    prep_all<<<ML + 2 * G3 + 1, 128>>>(sents, mtab, masks, lens, gWihf, gWihb); // 1
    zero_all<<<2048, 256>>>();                                                  // 2
    gemm_gi_tf32<<<dim3(6, 128, 2), 128>>>(gbihf, gbihb);                       // 3
    gru_persistent<<<128, 256>>>(lens, gWhhf, gWhhb, gbhhf, gbhhb);             // 4 <- ncu
    prep_tbeff<<<1, 32>>>(hb, tW, tb);                                          // 5
    prep_Wc<<<32, 256>>>(hW, tW);                                               // 6
    fk_kernel<<<1024, 256>>>();                                                 // 7
    crf_kernel<<<16, 128>>>(lens, trans);                                       // 8
    pool_kernel<<<dim3(B, NK), 512>>>();                                        // 9
    cls_kernel<<<B, 256>>>(lW, lb);                                             // 10
    loss_kernel<<<1, 128>>>(labels, out);                                       // 11
}

// round 6
// speedup vs baseline: 2.0940x; 1.6986x over previous
#include <cuda_runtime.h>
#include <math.h>
#include <stdint.h>

constexpr int B   = 128;
constexpr int L   = 128;
constexpr int D   = 300;
constexpr int MD  = 50;
constexpr int GIN = 350;
constexpr int GINP= 352;
constexpr int HD  = 256;
constexpr int G3  = 768;
constexpr int H   = 512;
constexpr int R   = 128;
constexpr int T   = 4;
constexpr int NK  = 4;
constexpr int ML  = B * L;

// ---- static scratch ----
__device__ float d_x[ML * GINP];
__device__ float d_Wp[2 * G3 * GINP];
__device__ float d_gi[2 * (size_t)ML * G3];
__device__ float d_h[2 * 2 * B * HD];
__device__ float d_ctx[(size_t)ML * H];
__device__ float d_wtab[ML];
__device__ float d_Wc[16 * H];
__device__ float d_fk[NK * ML * T];
__device__ float d_alpha[NK * ML * T];
__device__ float d_sp[NK * ML];
__device__ float d_spsum[NK * B];
__device__ float d_tbeff[NK * T];
__device__ float d_scores[B * 3];
__device__ int   d_flags[2 * 8 * 128 * 8];   // [dir][bg][t][gs]

__device__ __forceinline__ float sigm(float x) { return 1.f / (1.f + expf(-x)); }
__device__ __forceinline__ float lse4(float v0, float v1, float v2, float v3) {
    float mx = fmaxf(fmaxf(v0, v1), fmaxf(v2, v3));
    return mx + logf(expf(v0 - mx) + expf(v1 - mx) + expf(v2 - mx) + expf(v3 - mx));
}
__device__ __forceinline__ float tf32r(float x) {
    uint32_t u; asm("cvt.rna.tf32.f32 %0, %1;" : "=r"(u) : "f"(x));
    return __uint_as_float(u);
}
__device__ __forceinline__ void mma8(float* c, const uint32_t* a, const uint32_t* b) {
    asm("mma.sync.aligned.m16n8k8.row.col.f32.tf32.tf32.f32 "
        "{%0,%1,%2,%3},{%4,%5,%6,%7},{%8,%9},{%0,%1,%2,%3};"
        : "+f"(c[0]), "+f"(c[1]), "+f"(c[2]), "+f"(c[3])
        : "r"(a[0]), "r"(a[1]), "r"(a[2]), "r"(a[3]), "r"(b[0]), "r"(b[1]));
}

// ---- prep_all: x concat, W pad, pos-weights, zeroing (one launch) ----
constexpr int NB_X = ML, NB_W = 2 * G3, NB_MAIN = NB_X + NB_W + 1;
constexpr int NB_Z = 2048;
constexpr size_t CTX4 = (size_t)ML * H / 4;
constexpr size_t H4   = 2 * B * HD / 4;
constexpr size_t FL4  = sizeof(d_flags) / 16;
constexpr size_t ZT   = CTX4 + H4 + FL4;

__global__ void prep_all(const float* __restrict__ sents, const float* __restrict__ mtab,
                         const int* __restrict__ masks, const int* __restrict__ lens,
                         const float* __restrict__ Wf, const float* __restrict__ Wb) {
    const int bid = blockIdx.x;
    if (bid < NB_X) {
        const int row = bid;
        const int msk = masks[row];
        for (int k = threadIdx.x; k < GINP; k += blockDim.x) {
            float v;
            if (k < D)        v = sents[(size_t)row * D + k];
            else if (k < GIN) v = mtab[msk * MD + (k - D)];
            else              v = 0.f;
            d_x[(size_t)row * GINP + k] = v;
        }
    } else if (bid < NB_X + NB_W) {
        const int q = bid - NB_X;
        const int dd = q / G3, g = q % G3;
        const float* W = dd ? Wb : Wf;
        for (int k = threadIdx.x; k < GINP; k += blockDim.x)
            d_Wp[((size_t)dd * G3 + g) * GINP + k] = (k < GIN) ? W[(size_t)g * GIN + k] : 0.f;
    } else if (bid == NB_X + NB_W) {
        const int b = threadIdx.x;
        if (b >= B) return;
        int begin = 0, tnum = 0; bool found = false;
        for (int j = 0; j < L; j++) {
            int m = masks[b * L + j];
            tnum += m;
            if (!found && m == 1) { begin = j; found = true; }
        }
        const int len = lens[b];
        const float lf = (float)len;
        for (int j = 0; j < L; j++) {
            float w = (j < begin) ? (1.f - (float)(begin - j) / lf) : 0.f;
            if (masks[b * L + j] == 1) w = 1.f;
            if (j > begin + tnum) w = 1.f - (float)(j - begin) / lf;
            if (j > len) w = 0.f;
            d_wtab[b * L + j] = w;
        }
    } else {
        const int z = bid - NB_MAIN;
        float4 zz = {0.f, 0.f, 0.f, 0.f};
        for (size_t i = (size_t)z * 128 + threadIdx.x; i < ZT; i += (size_t)NB_Z * 128) {
            if (i < CTX4)            ((float4*)d_ctx)[i] = zz;
            else if (i < CTX4 + H4)  ((float4*)d_h)[i - CTX4] = zz;
            else                     ((float4*)d_flags)[i - CTX4 - H4] = zz;
        }
    }
}

// ---- prep_small: Wc = tW@hW fused weight + tb_eff ----
__global__ void prep_small(const float* __restrict__ hW, const float* __restrict__ tW,
                           const float* __restrict__ hb, const float* __restrict__ tb) {
    if (blockIdx.x < 32) {
        const int idx = blockIdx.x * 256 + threadIdx.x;   // 8192
        const int kb = idx >> 11, tt = (idx >> 9) & 3, h = idx & 511;
        float s = 0.f;
        for (int r = 0; r < R; r++)
            s += tW[(kb * T + tt) * R + r] * hW[((size_t)kb * R + r) * H + h];
        d_Wc[idx] = s;
    } else {
        const int i = threadIdx.x;
        if (i < NK * T) {
            const int kb = i >> 2;
            float s = tb[i];
            for (int r = 0; r < R; r++) s += hb[kb * R + r] * tW[i * R + r];
            d_tbeff[i] = s;
        }
    }
}

// ---- GEMM 1 (tf32): gi[dir][l*B+b][g] = x[b,l] @ Wp[dir]^T + bih ----
__global__ void __launch_bounds__(128) gemm_gi_tf32(const float* __restrict__ bihf,
                                                    const float* __restrict__ bihb) {
    __shared__ __align__(16) float a_s[128 * 20];
    __shared__ __align__(16) float b_s[128 * 20];
    const int tid = threadIdx.x;
    const int lane = tid & 31, warp = tid >> 5;
    const int n0 = blockIdx.x * 128;
    const int l  = blockIdx.y;
    const int dir = blockIdx.z;
    const int wm = (warp & 1) * 64, wn = (warp >> 1) * 64;
    const int lrow = tid >> 2, lc4 = (tid & 3) * 4;

    float acc[4][8][4];
#pragma unroll
    for (int i = 0; i < 4; i++)
#pragma unroll
        for (int j = 0; j < 8; j++)
#pragma unroll
            for (int q = 0; q < 4; q++) acc[i][j][q] = 0.f;

    for (int k0 = 0; k0 < GINP; k0 += 16) {
#pragma unroll
        for (int p = 0; p < 4; p++) {
            const int r = p * 32 + lrow;
            float4 va = *(const float4*)(d_x + ((size_t)r * L + l) * GINP + k0 + lc4);
            float4 vb = *(const float4*)(d_Wp + ((size_t)dir * G3 + n0 + r) * GINP + k0 + lc4);
            va.x = tf32r(va.x); va.y = tf32r(va.y); va.z = tf32r(va.z); va.w = tf32r(va.w);
            vb.x = tf32r(vb.x); vb.y = tf32r(vb.y); vb.z = tf32r(vb.z); vb.w = tf32r(vb.w);
            *(float4*)&a_s[r * 20 + lc4] = va;
            *(float4*)&b_s[r * 20 + lc4] = vb;
        }
        __syncthreads();
#pragma unroll
        for (int ks = 0; ks < 16; ks += 8) {
            uint32_t af[4][4], bf[8][2];
#pragma unroll
            for (int i = 0; i < 4; i++) {
                const int r0 = wm + i * 16 + (lane >> 2), cc = ks + (lane & 3);
                af[i][0] = __float_as_uint(a_s[r0 * 20 + cc]);
                af[i][1] = __float_as_uint(a_s[(r0 + 8) * 20 + cc]);
                af[i][2] = __float_as_uint(a_s[r0 * 20 + cc + 4]);
                af[i][3] = __float_as_uint(a_s[(r0 + 8) * 20 + cc + 4]);
            }
#pragma unroll
            for (int j = 0; j < 8; j++) {
                const int nn = wn + j * 8 + (lane >> 2), kk = ks + (lane & 3);
                bf[j][0] = __float_as_uint(b_s[nn * 20 + kk]);
                bf[j][1] = __float_as_uint(b_s[nn * 20 + kk + 4]);
            }
#pragma unroll
            for (int i = 0; i < 4; i++)
#pragma unroll
                for (int j = 0; j < 8; j++) mma8(acc[i][j], af[i], bf[j]);
        }
        __syncthreads();
    }
    const float* bih = dir ? bihb : bihf;
    float* C = d_gi + (size_t)dir * ML * G3 + (size_t)l * B * G3;
#pragma unroll
    for (int i = 0; i < 4; i++) {
        const int rb = wm + i * 16 + (lane >> 2);
#pragma unroll
        for (int j = 0; j < 8; j++) {
            const int nn = n0 + wn + j * 8 + 2 * (lane & 3);
            const float b0 = bih[nn], b1 = bih[nn + 1];
            float2 v0 = {acc[i][j][0] + b0, acc[i][j][1] + b1};
            float2 v1 = {acc[i][j][2] + b0, acc[i][j][3] + b1};
            *(float2*)(C + (size_t)rb * G3 + nn) = v0;
            *(float2*)(C + (size_t)(rb + 8) * G3 + nn) = v1;
        }
    }
}

// ---- gru_v2: 128 independent-flow blocks (2 dir x 8 gate-slices x 8 batch-groups)
// Block owns 32 units x 16 batch rows. tf32 mma for gates; flag-based dataflow sync.
__global__ void __launch_bounds__(128, 1) gru_v2(const int* __restrict__ lens,
                                                 const float* __restrict__ Whhf,
                                                 const float* __restrict__ Whhb,
                                                 const float* __restrict__ bhhf,
                                                 const float* __restrict__ bhhb) {
    extern __shared__ float sm[];
    float* w_s  = sm;                    // 96 x 260
    float* a_s  = sm + 96 * 260;         // 16 x 260
    float* gh_s = a_s + 16 * 260;        // 16 x 100
    float* bhh_s = gh_s + 16 * 100;      // 96
    int*   len_s = (int*)(bhh_s + 96);   // 16

    const int tid = threadIdx.x;
    const int bx = blockIdx.x;
    const int dir = bx >> 6;
    const int gs  = (bx >> 3) & 7;
    const int bg  = bx & 7;
    const int b0  = bg * 16;
    const float* Whh = dir ? Whhb : Whhf;
    const float* bhh = dir ? bhhb : bhhf;

    for (int q = tid; q < 96 * 64; q += 128) {
        const int n = q >> 6, c4 = (q & 63) * 4;
        const int grow = (n >> 5) * HD + gs * 32 + (n & 31);
        float4 v = *(const float4*)(Whh + (size_t)grow * HD + c4);
        v.x = tf32r(v.x); v.y = tf32r(v.y); v.z = tf32r(v.z); v.w = tf32r(v.w);
        *(float4*)&w_s[n * 260 + c4] = v;
    }
    if (tid < 96) bhh_s[tid] = bhh[(tid >> 5) * HD + gs * 32 + (tid & 31)];
    if (tid < 16) len_s[tid] = lens[b0 + tid];
    __syncthreads();

    const int lane = tid & 31, warp = tid >> 5;
    const int nb = warp * 24;
    const int r0 = lane >> 2, cb = lane & 3;
    const float* gi = d_gi + (size_t)dir * ML * G3;
    int* flg = d_flags + ((dir * 8 + bg) * 128) * 8;

    for (int t = 0; t < L; t++) {
        const int buf = t & 1;
        const float* hbase = d_h + buf * (2 * B * HD) + dir * (B * HD);
        float* hout = d_h + (buf ^ 1) * (2 * B * HD) + dir * (B * HD);

        if (t > 0) {
            if (tid < 8) {
                volatile int* f = (volatile int*)(flg + (t - 1) * 8 + tid);
                while (*f == 0) __nanosleep(32);
            }
            __threadfence();
            __syncthreads();
            // load 16 x 256 h tile: 512 items of 8 floats
#pragma unroll
            for (int i = 0; i < 4; i++) {
                const int q = tid + 128 * i;          // 0..511
                const int r = q >> 5;                 // 0..15
                const int c8 = (q & 31) * 8;          // 0..248
                float4 v0 = __ldcg((const float4*)(hbase + (size_t)(b0 + r) * HD + c8));
                float4 v1 = __ldcg((const float4*)(hbase + (size_t)(b0 + r) * HD + c8 + 4));
                v0.x = tf32r(v0.x); v0.y = tf32r(v0.y); v0.z = tf32r(v0.z); v0.w = tf32r(v0.w);
                v1.x = tf32r(v1.x); v1.y = tf32r(v1.y); v1.z = tf32r(v1.z); v1.w = tf32r(v1.w);
                *(float4*)&a_s[r * 260 + c8] = v0;
                *(float4*)&a_s[r * 260 + c8 + 4] = v1;
            }
            __syncthreads();

            float acc[3][4];
#pragma unroll
            for (int j = 0; j < 3; j++)
#pragma unroll
                for (int q = 0; q < 4; q++) acc[j][q] = 0.f;
#pragma unroll 4
            for (int kk = 0; kk < 32; kk++) {
                const int cc = kk * 8 + cb;
                uint32_t a[4];
                a[0] = __float_as_uint(a_s[r0 * 260 + cc]);
                a[1] = __float_as_uint(a_s[(r0 + 8) * 260 + cc]);
                a[2] = __float_as_uint(a_s[r0 * 260 + cc + 4]);
                a[3] = __float_as_uint(a_s[(r0 + 8) * 260 + cc + 4]);
#pragma unroll
                for (int j = 0; j < 3; j++) {
                    const int nn = nb + j * 8 + r0;
                    uint32_t bb[2];
                    bb[0] = __float_as_uint(w_s[nn * 260 + cc]);
                    bb[1] = __float_as_uint(w_s[nn * 260 + cc + 4]);
                    mma8(acc[j], a, bb);
                }
            }
            __syncthreads();
#pragma unroll
            for (int j = 0; j < 3; j++) {
                const int n0c = nb + j * 8 + 2 * cb;
                gh_s[r0 * 100 + n0c]           = acc[j][0];
                gh_s[r0 * 100 + n0c + 1]       = acc[j][1];
                gh_s[(r0 + 8) * 100 + n0c]     = acc[j][2];
                gh_s[(r0 + 8) * 100 + n0c + 1] = acc[j][3];
            }
        } else {
            for (int q = tid; q < 1600; q += 128) gh_s[q] = 0.f;
        }
        __syncthreads();

#pragma unroll
        for (int i = 0; i < 4; i++) {
            const int item = tid + 128 * i;
            const int bl = item >> 5, ul = item & 31;
            const int b = b0 + bl;
            const int len = len_s[bl];
            const int ugl = gs * 32 + ul;
            const float hprev = __ldcg(hbase + (size_t)b * HD + ugl);
            float hnext = hprev;
            if (t < len) {
                const int pos = dir ? (len - 1 - t) : t;
                const float* gp = gi + ((size_t)pos * B + b) * G3;
                const float rr = sigm(gp[ugl] + gh_s[bl * 100 + ul] + bhh_s[ul]);
                const float zz = sigm(gp[256 + ugl] + gh_s[bl * 100 + 32 + ul] + bhh_s[32 + ul]);
                const float nn = tanhf(gp[512 + ugl] + rr * (gh_s[bl * 100 + 64 + ul] + bhh_s[64 + ul]));
                hnext = (1.f - zz) * nn + zz * hprev;
                d_ctx[((size_t)b * L + pos) * H + dir * HD + ugl] = hnext * d_wtab[b * L + pos];
            }
            hout[(size_t)b * HD + ugl] = hnext;
        }
        __syncthreads();
        if (tid == 0) {
            __threadfence();
            *(volatile int*)(flg + t * 8 + gs) = 1;
        }
    }
}

// ---- fk = ctx @ Wc^T + tbeff ----
__global__ void __launch_bounds__(256) fk_kernel() {
    const int idx = blockIdx.x * 256 + threadIdx.x;
    const int m = idx >> 4, o = idx & 15;
    const float4* cx = (const float4*)(d_ctx + (size_t)m * H);
    const float4* w  = (const float4*)(d_Wc + (size_t)o * H);
    float s = d_tbeff[o];
#pragma unroll 4
    for (int k = 0; k < H / 4; k++) {
        float4 c = cx[k], ww = w[k];
        s += c.x * ww.x + c.y * ww.y + c.z * ww.z + c.w * ww.w;
    }
    d_fk[((size_t)(o >> 2) * ML + m) * T + (o & 3)] = s;
}

// ---- CRF forward-backward marginals ----
__global__ void __launch_bounds__(128) crf_kernel(const int* __restrict__ lens,
                                                  const float* __restrict__ trans) {
    const int tid = threadIdx.x;
    const int tag = tid & 3;
    const int chain = blockIdx.x * 32 + (tid >> 2);
    const int kb = chain >> 7;
    const int b  = chain & 127;
    const int len = lens[b];
    const unsigned fm = 0xffffffffu;
    const int base = (tid & 31) & ~3;

    float tcol[4], trow[4];
#pragma unroll
    for (int i = 0; i < 4; i++) {
        tcol[i] = trans[kb * 16 + i * 4 + tag];
        trow[i] = trans[kb * 16 + tag * 4 + i];
    }
    const float* f = d_fk + ((size_t)kb * ML + (size_t)b * L) * T;
    float* al = d_alpha + ((size_t)kb * ML + (size_t)b * L) * T;

    float alpha = f[tag];
    al[tag] = alpha;
    for (int l = 1; l < L; l++) {
        float a0 = __shfl_sync(fm, alpha, base + 0);
        float a1 = __shfl_sync(fm, alpha, base + 1);
        float a2 = __shfl_sync(fm, alpha, base + 2);
        float a3 = __shfl_sync(fm, alpha, base + 3);
        float na = lse4(a0 + tcol[0], a1 + tcol[1], a2 + tcol[2], a3 + tcol[3]) + f[l * T + tag];
        if (l < len) alpha = na;
        al[l * T + tag] = alpha;
    }
    float beta = 0.f, ssum = 0.f;
    float* sp = d_sp + (size_t)(kb * B + b) * L;
    for (int l = L - 1; l >= 0; l--) {
        float v = al[l * T + tag] + beta;
        float v0 = __shfl_sync(fm, v, base + 0);
        float v1 = __shfl_sync(fm, v, base + 1);
        float v2 = __shfl_sync(fm, v, base + 2);
        float v3 = __shfl_sync(fm, v, base + 3);
        float p1 = expf(v1 - lse4(v0, v1, v2, v3));
        float spl = (l < len) ? p1 : 0.f;
        ssum += spl;
        if (tag == 0) sp[l] = spl;
        if (l >= 1) {
            float fb = f[l * T + tag] + beta;
            float c0 = __shfl_sync(fm, fb, base + 0);
            float c1 = __shfl_sync(fm, fb, base + 1);
            float c2 = __shfl_sync(fm, fb, base + 2);
            float c3 = __shfl_sync(fm, fb, base + 3);
            float nb2 = lse4(trow[0] + c0, trow[1] + c1, trow[2] + c2, trow[3] + c3);
            if (l < len) beta = nb2;
        }
    }
    if (tag == 0) d_spsum[kb * B + b] = ssum;
}

// ---- pooling + classifier fused ----
__global__ void __launch_bounds__(512) poolcls(const float* __restrict__ lW,
                                               const float* __restrict__ lb) {
    const int b = blockIdx.x, tid = threadIdx.x;
    __shared__ float spn[512];
    __shared__ float red[3][512];
    {
        const int kb = tid >> 7, l = tid & 127;
        spn[tid] = d_sp[(size_t)(kb * B + b) * L + l] / d_spsum[kb * B + b];
    }
    __syncthreads();
    float a0 = 0.f, a1 = 0.f, a2 = 0.f, a3 = 0.f;
    const float* c = d_ctx + (size_t)b * L * H + tid;
    for (int l = 0; l < 128; l++) {
        float cv = c[(size_t)l * H];
        a0 += spn[l] * cv; a1 += spn[128 + l] * cv;
        a2 += spn[256 + l] * cv; a3 += spn[384 + l] * cv;
    }
    float p0 = 0.f, p1 = 0.f, p2 = 0.f, s;
    s = fmaxf(a0, 0.f); p0 += s * lW[tid];        p1 += s * lW[2048 + tid];        p2 += s * lW[4096 + tid];
    s = fmaxf(a1, 0.f); p0 += s * lW[512 + tid];  p1 += s * lW[2560 + tid];        p2 += s * lW[4608 + tid];
    s = fmaxf(a2, 0.f); p0 += s * lW[1024 + tid]; p1 += s * lW[3072 + tid];        p2 += s * lW[5120 + tid];
    s = fmaxf(a3, 0.f); p0 += s * lW[1536 + tid]; p1 += s * lW[3584 + tid];        p2 += s * lW[5632 + tid];
    red[0][tid] = p0; red[1][tid] = p1; red[2][tid] = p2;
    __syncthreads();
    for (int off = 256; off > 0; off >>= 1) {
        if (tid < off) {
            red[0][tid] += red[0][tid + off];
            red[1][tid] += red[1][tid + off];
            red[2][tid] += red[2][tid + off];
        }
        __syncthreads();
    }
    if (tid < 3) d_scores[b * 3 + tid] = red[tid][0] + lb[tid];
}

__global__ void __launch_bounds__(128) loss_kernel(const int* __restrict__ labels,
                                                   float* __restrict__ out) {
    __shared__ float red[128];
    const int b = threadIdx.x;
    float s0 = d_scores[b * 3], s1 = d_scores[b * 3 + 1], s2 = d_scores[b * 3 + 2];
    float m = fmaxf(s0, fmaxf(s1, s2));
    float lse = m + logf(expf(s0 - m) + expf(s1 - m) + expf(s2 - m));
    int lab = labels[b];
    float sl = (lab == 0) ? s0 : ((lab == 1) ? s1 : s2);
    red[b] = lse - sl;
    __syncthreads();
    for (int off = 64; off > 0; off >>= 1) {
        if (b < off) red[b] += red[b + off];
        __syncthreads();
    }
    if (b == 0) out[0] = red[0] / (float)B;
}

extern "C" void kernel_launch(void* const* d_in, const int* in_sizes, int n_in,
                              void* d_out, int out_size) {
    (void)in_sizes; (void)n_in; (void)out_size;
    const float* sents = (const float*)d_in[0];
    const float* mtab  = (const float*)d_in[1];
    const float* gWihf = (const float*)d_in[2];
    const float* gWhhf = (const float*)d_in[3];
    const float* gbihf = (const float*)d_in[4];
    const float* gbhhf = (const float*)d_in[5];
    const float* gWihb = (const float*)d_in[6];
    const float* gWhhb = (const float*)d_in[7];
    const float* gbihb = (const float*)d_in[8];
    const float* gbhhb = (const float*)d_in[9];
    const float* hW    = (const float*)d_in[10];
    const float* hb    = (const float*)d_in[11];
    const float* tW    = (const float*)d_in[12];
    const float* tb    = (const float*)d_in[13];
    const float* trans = (const float*)d_in[14];
    const float* lW    = (const float*)d_in[15];
    const float* lb    = (const float*)d_in[16];
    const int* masks   = (const int*)d_in[17];
    const int* lens    = (const int*)d_in[18];
    const int* labels  = (const int*)d_in[19];
    float* out = (float*)d_out;

    const int smem_gru = (96 * 260 + 16 * 260 + 16 * 100 + 96) * 4 + 16 * 4;
    cudaFuncSetAttribute(gru_v2, cudaFuncAttributeMaxDynamicSharedMemorySize, smem_gru);

    prep_all<<<NB_MAIN + NB_Z, 128>>>(sents, mtab, masks, lens, gWihf, gWihb);  // 1
    prep_small<<<33, 256>>>(hW, tW, hb, tb);                                     // 2
    gemm_gi_tf32<<<dim3(6, 128, 2), 128>>>(gbihf, gbihb);                        // 3
    gru_v2<<<128, 128, smem_gru>>>(lens, gWhhf, gWhhb, gbhhf, gbhhb);            // 4 <- ncu
    fk_kernel<<<1024, 256>>>();                                                  // 5
    crf_kernel<<<16, 128>>>(lens, trans);                                        // 6
    poolcls<<<B, 512>>>(lW, lb);                                                 // 7
    loss_kernel<<<1, 128>>>(labels, out);                                        // 8
}

// round 7
// speedup vs baseline: 4.0209x; 1.9202x over previous
#include <cuda_runtime.h>
#include <math.h>
#include <stdint.h>

constexpr int B   = 128;
constexpr int L   = 128;
constexpr int D   = 300;
constexpr int MD  = 50;
constexpr int GIN = 350;
constexpr int GINP= 352;
constexpr int HD  = 256;
constexpr int G3  = 768;
constexpr int H   = 512;
constexpr int R   = 128;
constexpr int T   = 4;
constexpr int NK  = 4;
constexpr int ML  = B * L;

// ---- static scratch ----
__device__ float d_x[ML * GINP];
__device__ float d_Wp[2 * G3 * GINP];
__device__ float d_gi[2 * (size_t)ML * G3];
__device__ float d_h[2 * 2 * B * HD];
__device__ float d_ctx[(size_t)ML * H];
__device__ float d_wtab[ML];
__device__ float d_Wc[16 * H];
__device__ float d_fk[NK * ML * T];
__device__ float d_alpha[NK * ML * T];
__device__ float d_sp[NK * ML];
__device__ float d_spsum[NK * B];
__device__ float d_tbeff[NK * T];
__device__ float d_scores[B * 3];
__device__ int   d_flags[2 * 8 * 128 * 8];   // [dir][bg][t][gs]

__device__ __forceinline__ float lse4(float v0, float v1, float v2, float v3) {
    float mx = fmaxf(fmaxf(v0, v1), fmaxf(v2, v3));
    return mx + logf(expf(v0 - mx) + expf(v1 - mx) + expf(v2 - mx) + expf(v3 - mx));
}
__device__ __forceinline__ float tf32r(float x) {
    uint32_t u; asm("cvt.rna.tf32.f32 %0, %1;" : "=r"(u) : "f"(x));
    return __uint_as_float(u);
}
__device__ __forceinline__ float tanha(float x) {
    float r; asm("tanh.approx.f32 %0, %1;" : "=f"(r) : "f"(x)); return r;
}
__device__ __forceinline__ float sigma(float x) {   // sigmoid via hw tanh
    return fmaf(0.5f, tanha(0.5f * x), 0.5f);
}
__device__ __forceinline__ void mma8(float* c, const uint32_t* a, const uint32_t* b) {
    asm("mma.sync.aligned.m16n8k8.row.col.f32.tf32.tf32.f32 "
        "{%0,%1,%2,%3},{%4,%5,%6,%7},{%8,%9},{%0,%1,%2,%3};"
        : "+f"(c[0]), "+f"(c[1]), "+f"(c[2]), "+f"(c[3])
        : "r"(a[0]), "r"(a[1]), "r"(a[2]), "r"(a[3]), "r"(b[0]), "r"(b[1]));
}

// ---- prep_all: x concat, W pad, pos-weights, zeroing (one launch) ----
constexpr int NB_X = ML, NB_W = 2 * G3, NB_MAIN = NB_X + NB_W + 1;
constexpr int NB_Z = 2048;
constexpr size_t CTX4 = (size_t)ML * H / 4;
constexpr size_t H4   = 2 * B * HD / 4;
constexpr size_t FL4  = sizeof(d_flags) / 16;
constexpr size_t ZT   = CTX4 + H4 + FL4;

__global__ void prep_all(const float* __restrict__ sents, const float* __restrict__ mtab,
                         const int* __restrict__ masks, const int* __restrict__ lens,
                         const float* __restrict__ Wf, const float* __restrict__ Wb) {
    const int bid = blockIdx.x;
    if (bid < NB_X) {
        const int row = bid;
        const int msk = masks[row];
        for (int k = threadIdx.x; k < GINP; k += blockDim.x) {
            float v;
            if (k < D)        v = sents[(size_t)row * D + k];
            else if (k < GIN) v = mtab[msk * MD + (k - D)];
            else              v = 0.f;
            d_x[(size_t)row * GINP + k] = v;
        }
    } else if (bid < NB_X + NB_W) {
        const int q = bid - NB_X;
        const int dd = q / G3, g = q % G3;
        const float* W = dd ? Wb : Wf;
        for (int k = threadIdx.x; k < GINP; k += blockDim.x)
            d_Wp[((size_t)dd * G3 + g) * GINP + k] = (k < GIN) ? W[(size_t)g * GIN + k] : 0.f;
    } else if (bid == NB_X + NB_W) {
        const int b = threadIdx.x;
        if (b >= B) return;
        int begin = 0, tnum = 0; bool found = false;
        for (int j = 0; j < L; j++) {
            int m = masks[b * L + j];
            tnum += m;
            if (!found && m == 1) { begin = j; found = true; }
        }
        const int len = lens[b];
        const float lf = (float)len;
        for (int j = 0; j < L; j++) {
            float w = (j < begin) ? (1.f - (float)(begin - j) / lf) : 0.f;
            if (masks[b * L + j] == 1) w = 1.f;
            if (j > begin + tnum) w = 1.f - (float)(j - begin) / lf;
            if (j > len) w = 0.f;
            d_wtab[b * L + j] = w;
        }
    } else {
        const int z = bid - NB_MAIN;
        float4 zz = {0.f, 0.f, 0.f, 0.f};
        for (size_t i = (size_t)z * 128 + threadIdx.x; i < ZT; i += (size_t)NB_Z * 128) {
            if (i < CTX4)            ((float4*)d_ctx)[i] = zz;
            else if (i < CTX4 + H4)  ((float4*)d_h)[i - CTX4] = zz;
            else                     ((float4*)d_flags)[i - CTX4 - H4] = zz;
        }
    }
}

// ---- prep_small: Wc = tW@hW fused weight + tb_eff ----
__global__ void prep_small(const float* __restrict__ hW, const float* __restrict__ tW,
                           const float* __restrict__ hb, const float* __restrict__ tb) {
    if (blockIdx.x < 32) {
        const int idx = blockIdx.x * 256 + threadIdx.x;   // 8192
        const int kb = idx >> 11, tt = (idx >> 9) & 3, h = idx & 511;
        float s = 0.f;
        for (int r = 0; r < R; r++)
            s += tW[(kb * T + tt) * R + r] * hW[((size_t)kb * R + r) * H + h];
        d_Wc[idx] = s;
    } else {
        const int i = threadIdx.x;
        if (i < NK * T) {
            const int kb = i >> 2;
            float s = tb[i];
            for (int r = 0; r < R; r++) s += hb[kb * R + r] * tW[i * R + r];
            d_tbeff[i] = s;
        }
    }
}

// ---- GEMM 1 (tf32): gi[dir][l*B+b][g] = x[b,l] @ Wp[dir]^T + bih ----
__global__ void __launch_bounds__(128) gemm_gi_tf32(const float* __restrict__ bihf,
                                                    const float* __restrict__ bihb) {
    __shared__ __align__(16) float a_s[128 * 20];
    __shared__ __align__(16) float b_s[128 * 20];
    const int tid = threadIdx.x;
    const int lane = tid & 31, warp = tid >> 5;
    const int n0 = blockIdx.x * 128;
    const int l  = blockIdx.y;
    const int dir = blockIdx.z;
    const int wm = (warp & 1) * 64, wn = (warp >> 1) * 64;
    const int lrow = tid >> 2, lc4 = (tid & 3) * 4;

    float acc[4][8][4];
#pragma unroll
    for (int i = 0; i < 4; i++)
#pragma unroll
        for (int j = 0; j < 8; j++)
#pragma unroll
            for (int q = 0; q < 4; q++) acc[i][j][q] = 0.f;

    for (int k0 = 0; k0 < GINP; k0 += 16) {
#pragma unroll
        for (int p = 0; p < 4; p++) {
            const int r = p * 32 + lrow;
            float4 va = *(const float4*)(d_x + ((size_t)r * L + l) * GINP + k0 + lc4);
            float4 vb = *(const float4*)(d_Wp + ((size_t)dir * G3 + n0 + r) * GINP + k0 + lc4);
            va.x = tf32r(va.x); va.y = tf32r(va.y); va.z = tf32r(va.z); va.w = tf32r(va.w);
            vb.x = tf32r(vb.x); vb.y = tf32r(vb.y); vb.z = tf32r(vb.z); vb.w = tf32r(vb.w);
            *(float4*)&a_s[r * 20 + lc4] = va;
            *(float4*)&b_s[r * 20 + lc4] = vb;
        }
        __syncthreads();
#pragma unroll
        for (int ks = 0; ks < 16; ks += 8) {
            uint32_t af[4][4], bf[8][2];
#pragma unroll
            for (int i = 0; i < 4; i++) {
                const int r0 = wm + i * 16 + (lane >> 2), cc = ks + (lane & 3);
                af[i][0] = __float_as_uint(a_s[r0 * 20 + cc]);
                af[i][1] = __float_as_uint(a_s[(r0 + 8) * 20 + cc]);
                af[i][2] = __float_as_uint(a_s[r0 * 20 + cc + 4]);
                af[i][3] = __float_as_uint(a_s[(r0 + 8) * 20 + cc + 4]);
            }
#pragma unroll
            for (int j = 0; j < 8; j++) {
                const int nn = wn + j * 8 + (lane >> 2), kk = ks + (lane & 3);
                bf[j][0] = __float_as_uint(b_s[nn * 20 + kk]);
                bf[j][1] = __float_as_uint(b_s[nn * 20 + kk + 4]);
            }
#pragma unroll
            for (int i = 0; i < 4; i++)
#pragma unroll
                for (int j = 0; j < 8; j++) mma8(acc[i][j], af[i], bf[j]);
        }
        __syncthreads();
    }
    const float* bih = dir ? bihb : bihf;
    float* C = d_gi + (size_t)dir * ML * G3 + (size_t)l * B * G3;
#pragma unroll
    for (int i = 0; i < 4; i++) {
        const int rb = wm + i * 16 + (lane >> 2);
#pragma unroll
        for (int j = 0; j < 8; j++) {
            const int nn = n0 + wn + j * 8 + 2 * (lane & 3);
            const float b0 = bih[nn], b1 = bih[nn + 1];
            float2 v0 = {acc[i][j][0] + b0, acc[i][j][1] + b1};
            float2 v1 = {acc[i][j][2] + b0, acc[i][j][3] + b1};
            *(float2*)(C + (size_t)rb * G3 + nn) = v0;
            *(float2*)(C + (size_t)(rb + 8) * G3 + nn) = v1;
        }
    }
}

// ---- gru_v3: 128 dataflow blocks (2 dir x 8 gate-slices x 8 batch-groups).
// Gate-aligned fragments: warp w owns units w*8..w*8+7 for ALL 3 gates, so
// r/z/n of an item live in one thread. HW tanh approx for activations.
__global__ void __launch_bounds__(128, 1) gru_v3(const int* __restrict__ lens,
                                                 const float* __restrict__ Whhf,
                                                 const float* __restrict__ Whhb,
                                                 const float* __restrict__ bhhf,
                                                 const float* __restrict__ bhhb) {
    extern __shared__ float sm[];
    float* w_s   = sm;                     // [96][260]  (gate-major: [3][32][260])
    float* a_s   = sm + 96 * 260;          // [16][260]  tf32-rounded h tile
    float* hraw  = a_s + 16 * 260;         // [16][36]   raw h for this gs slice
    int*   len_s = (int*)(hraw + 16 * 36); // [16]

    const int tid = threadIdx.x;
    const int bx = blockIdx.x;
    const int dir = bx >> 6;
    const int gs  = (bx >> 3) & 7;
    const int bg  = bx & 7;
    const int b0  = bg * 16;
    const float* Whh = dir ? Whhb : Whhf;
    const float* bhh = dir ? bhhb : bhhf;

    for (int q = tid; q < 96 * 64; q += 128) {
        const int n = q >> 6, c4 = (q & 63) * 4;     // n: g=n>>5, u=n&31
        const int grow = (n >> 5) * HD + gs * 32 + (n & 31);
        float4 v = *(const float4*)(Whh + (size_t)grow * HD + c4);
        v.x = tf32r(v.x); v.y = tf32r(v.y); v.z = tf32r(v.z); v.w = tf32r(v.w);
        *(float4*)&w_s[n * 260 + c4] = v;
    }
    if (tid < 16) len_s[tid] = lens[b0 + tid];
    __syncthreads();

    const int lane = tid & 31, warp = tid >> 5;
    const int r0 = lane >> 2, cb = lane & 3;
    const int ul = warp * 8 + 2 * cb;           // unit within gs slice (even)
    const int ug = gs * 32 + ul;                // unit within direction
    const float bR0 = bhh[ug],        bR1 = bhh[ug + 1];
    const float bZ0 = bhh[256 + ug],  bZ1 = bhh[256 + ug + 1];
    const float bN0 = bhh[512 + ug],  bN1 = bhh[512 + ug + 1];
    const float* gi = d_gi + (size_t)dir * ML * G3;
    int* flg = d_flags + ((dir * 8 + bg) * 128) * 8;

    const int lenA = len_s[r0], lenB = len_s[r0 + 8];

    for (int t = 0; t < L; t++) {
        const int buf = t & 1;
        const float* hbase = d_h + buf * (2 * B * HD) + dir * (B * HD);
        float* hout = d_h + (buf ^ 1) * (2 * B * HD) + dir * (B * HD);

        // prefetch gi for this step (independent of h / flags)
        float2 gr[2], gz[2], gn[2];
        int posv[2]; bool act[2];
        {
            const int lenv[2] = {lenA, lenB};
#pragma unroll
            for (int s = 0; s < 2; s++) {
                act[s] = (t < lenv[s]);
                posv[s] = dir ? (lenv[s] - 1 - t) : t;
                if (act[s]) {
                    const float* gp = gi + ((size_t)posv[s] * B + (b0 + r0 + 8 * s)) * G3;
                    gr[s] = *(const float2*)(gp + ug);
                    gz[s] = *(const float2*)(gp + 256 + ug);
                    gn[s] = *(const float2*)(gp + 512 + ug);
                }
            }
        }

        float acc[3][4];
#pragma unroll
        for (int j = 0; j < 3; j++)
#pragma unroll
            for (int q = 0; q < 4; q++) acc[j][q] = 0.f;

        if (t > 0) {
            if (tid < 8) {
                volatile int* f = (volatile int*)(flg + (t - 1) * 8 + tid);
                while (*f == 0) {}
                __threadfence();
            }
            __syncthreads();
            // load 16 x 256 h tile; stash raw slice for hprev
#pragma unroll
            for (int i = 0; i < 4; i++) {
                const int q = tid + 128 * i;          // 0..511
                const int r = q >> 5;                 // 0..15
                const int ch = q & 31;                // 8-col chunk
                const int c8 = ch * 8;
                float4 v0 = __ldcg((const float4*)(hbase + (size_t)(b0 + r) * HD + c8));
                float4 v1 = __ldcg((const float4*)(hbase + (size_t)(b0 + r) * HD + c8 + 4));
                if ((ch >> 2) == gs) {
                    const int off = c8 - gs * 32;
                    *(float4*)&hraw[r * 36 + off] = v0;
                    *(float4*)&hraw[r * 36 + off + 4] = v1;
                }
                v0.x = tf32r(v0.x); v0.y = tf32r(v0.y); v0.z = tf32r(v0.z); v0.w = tf32r(v0.w);
                v1.x = tf32r(v1.x); v1.y = tf32r(v1.y); v1.z = tf32r(v1.z); v1.w = tf32r(v1.w);
                *(float4*)&a_s[r * 260 + c8] = v0;
                *(float4*)&a_s[r * 260 + c8 + 4] = v1;
            }
            __syncthreads();

#pragma unroll 4
            for (int kk = 0; kk < 32; kk++) {
                const int cc = kk * 8 + cb;
                uint32_t a[4];
                a[0] = __float_as_uint(a_s[r0 * 260 + cc]);
                a[1] = __float_as_uint(a_s[(r0 + 8) * 260 + cc]);
                a[2] = __float_as_uint(a_s[r0 * 260 + cc + 4]);
                a[3] = __float_as_uint(a_s[(r0 + 8) * 260 + cc + 4]);
#pragma unroll
                for (int j = 0; j < 3; j++) {
                    const int nn = j * 32 + warp * 8 + r0;   // gate-aligned B rows
                    uint32_t bb[2];
                    bb[0] = __float_as_uint(w_s[nn * 260 + cc]);
                    bb[1] = __float_as_uint(w_s[nn * 260 + cc + 4]);
                    mma8(acc[j], a, bb);
                }
            }
        }

        // elementwise in registers
#pragma unroll
        for (int s = 0; s < 2; s++) {
            const int r = r0 + 8 * s;
            const int b = b0 + r;
            float2 hp;
            if (t > 0) hp = *(const float2*)&hraw[r * 36 + ul];
            else { hp.x = 0.f; hp.y = 0.f; }
            float2 hn = hp;
            if (act[s]) {
                const float rrx = sigma(gr[s].x + acc[0][2 * s]     + bR0);
                const float rry = sigma(gr[s].y + acc[0][2 * s + 1] + bR1);
                const float zzx = sigma(gz[s].x + acc[1][2 * s]     + bZ0);
                const float zzy = sigma(gz[s].y + acc[1][2 * s + 1] + bZ1);
                const float nnx = tanha(gn[s].x + rrx * (acc[2][2 * s]     + bN0));
                const float nny = tanha(gn[s].y + rry * (acc[2][2 * s + 1] + bN1));
                hn.x = (1.f - zzx) * nnx + zzx * hp.x;
                hn.y = (1.f - zzy) * nny + zzy * hp.y;
                const int pos = posv[s];
                const float wt = d_wtab[b * L + pos];
                float2 cv = {hn.x * wt, hn.y * wt};
                *(float2*)(d_ctx + ((size_t)b * L + pos) * H + dir * HD + ug) = cv;
            }
            *(float2*)(hout + (size_t)b * HD + ug) = hn;
        }

        __syncthreads();
        if (tid == 0) {
            __threadfence();
            *(volatile int*)(flg + t * 8 + gs) = 1;
        }
    }
}

// ---- fk = ctx @ Wc^T + tbeff ----
__global__ void __launch_bounds__(256) fk_kernel() {
    const int idx = blockIdx.x * 256 + threadIdx.x;
    const int m = idx >> 4, o = idx & 15;
    const float4* cx = (const float4*)(d_ctx + (size_t)m * H);
    const float4* w  = (const float4*)(d_Wc + (size_t)o * H);
    float s = d_tbeff[o];
#pragma unroll 4
    for (int k = 0; k < H / 4; k++) {
        float4 c = cx[k], ww = w[k];
        s += c.x * ww.x + c.y * ww.y + c.z * ww.z + c.w * ww.w;
    }
    d_fk[((size_t)(o >> 2) * ML + m) * T + (o & 3)] = s;
}

// ---- CRF forward-backward marginals ----
__global__ void __launch_bounds__(128) crf_kernel(const int* __restrict__ lens,
                                                  const float* __restrict__ trans) {
    const int tid = threadIdx.x;
    const int tag = tid & 3;
    const int chain = blockIdx.x * 32 + (tid >> 2);
    const int kb = chain >> 7;
    const int b  = chain & 127;
    const int len = lens[b];
    const unsigned fm = 0xffffffffu;
    const int base = (tid & 31) & ~3;

    float tcol[4], trow[4];
#pragma unroll
    for (int i = 0; i < 4; i++) {
        tcol[i] = trans[kb * 16 + i * 4 + tag];
        trow[i] = trans[kb * 16 + tag * 4 + i];
    }
    const float* f = d_fk + ((size_t)kb * ML + (size_t)b * L) * T;
    float* al = d_alpha + ((size_t)kb * ML + (size_t)b * L) * T;

    float alpha = f[tag];
    al[tag] = alpha;
    for (int l = 1; l < L; l++) {
        float a0 = __shfl_sync(fm, alpha, base + 0);
        float a1 = __shfl_sync(fm, alpha, base + 1);
        float a2 = __shfl_sync(fm, alpha, base + 2);
        float a3 = __shfl_sync(fm, alpha, base + 3);
        float na = lse4(a0 + tcol[0], a1 + tcol[1], a2 + tcol[2], a3 + tcol[3]) + f[l * T + tag];
        if (l < len) alpha = na;
        al[l * T + tag] = alpha;
    }
    float beta = 0.f, ssum = 0.f;
    float* sp = d_sp + (size_t)(kb * B + b) * L;
    for (int l = L - 1; l >= 0; l--) {
        float v = al[l * T + tag] + beta;
        float v0 = __shfl_sync(fm, v, base + 0);
        float v1 = __shfl_sync(fm, v, base + 1);
        float v2 = __shfl_sync(fm, v, base + 2);
        float v3 = __shfl_sync(fm, v, base + 3);
        float p1 = expf(v1 - lse4(v0, v1, v2, v3));
        float spl = (l < len) ? p1 : 0.f;
        ssum += spl;
        if (tag == 0) sp[l] = spl;
        if (l >= 1) {
            float fb = f[l * T + tag] + beta;
            float c0 = __shfl_sync(fm, fb, base + 0);
            float c1 = __shfl_sync(fm, fb, base + 1);
            float c2 = __shfl_sync(fm, fb, base + 2);
            float c3 = __shfl_sync(fm, fb, base + 3);
            float nb2 = lse4(trow[0] + c0, trow[1] + c1, trow[2] + c2, trow[3] + c3);
            if (l < len) beta = nb2;
        }
    }
    if (tag == 0) d_spsum[kb * B + b] = ssum;
}

// ---- pooling + classifier fused ----
__global__ void __launch_bounds__(512) poolcls(const float* __restrict__ lW,
                                               const float* __restrict__ lb) {
    const int b = blockIdx.x, tid = threadIdx.x;
    __shared__ float spn[512];
    __shared__ float red[3][512];
    {
        const int kb = tid >> 7, l = tid & 127;
        spn[tid] = d_sp[(size_t)(kb * B + b) * L + l] / d_spsum[kb * B + b];
    }
    __syncthreads();
    float a0 = 0.f, a1 = 0.f, a2 = 0.f, a3 = 0.f;
    const float* c = d_ctx + (size_t)b * L * H + tid;
    for (int l = 0; l < 128; l++) {
        float cv = c[(size_t)l * H];
        a0 += spn[l] * cv; a1 += spn[128 + l] * cv;
        a2 += spn[256 + l] * cv; a3 += spn[384 + l] * cv;
    }
    float p0 = 0.f, p1 = 0.f, p2 = 0.f, s;
    s = fmaxf(a0, 0.f); p0 += s * lW[tid];        p1 += s * lW[2048 + tid];        p2 += s * lW[4096 + tid];
    s = fmaxf(a1, 0.f); p0 += s * lW[512 + tid];  p1 += s * lW[2560 + tid];        p2 += s * lW[4608 + tid];
    s = fmaxf(a2, 0.f); p0 += s * lW[1024 + tid]; p1 += s * lW[3072 + tid];        p2 += s * lW[5120 + tid];
    s = fmaxf(a3, 0.f); p0 += s * lW[1536 + tid]; p1 += s * lW[3584 + tid];        p2 += s * lW[5632 + tid];
    red[0][tid] = p0; red[1][tid] = p1; red[2][tid] = p2;
    __syncthreads();
    for (int off = 256; off > 0; off >>= 1) {
        if (tid < off) {
            red[0][tid] += red[0][tid + off];
            red[1][tid] += red[1][tid + off];
            red[2][tid] += red[2][tid + off];
        }
        __syncthreads();
    }
    if (tid < 3) d_scores[b * 3 + tid] = red[tid][0] + lb[tid];
}

__global__ void __launch_bounds__(128) loss_kernel(const int* __restrict__ labels,
                                                   float* __restrict__ out) {
    __shared__ float red[128];
    const int b = threadIdx.x;
    float s0 = d_scores[b * 3], s1 = d_scores[b * 3 + 1], s2 = d_scores[b * 3 + 2];
    float m = fmaxf(s0, fmaxf(s1, s2));
    float lse = m + logf(expf(s0 - m) + expf(s1 - m) + expf(s2 - m));
    int lab = labels[b];
    float sl = (lab == 0) ? s0 : ((lab == 1) ? s1 : s2);
    red[b] = lse - sl;
    __syncthreads();
    for (int off = 64; off > 0; off >>= 1) {
        if (b < off) red[b] += red[b + off];
        __syncthreads();
    }
    if (b == 0) out[0] = red[0] / (float)B;
}

extern "C" void kernel_launch(void* const* d_in, const int* in_sizes, int n_in,
                              void* d_out, int out_size) {
    (void)in_sizes; (void)n_in; (void)out_size;
    const float* sents = (const float*)d_in[0];
    const float* mtab  = (const float*)d_in[1];
    const float* gWihf = (const float*)d_in[2];
    const float* gWhhf = (const float*)d_in[3];
    const float* gbihf = (const float*)d_in[4];
    const float* gbhhf = (const float*)d_in[5];
    const float* gWihb = (const float*)d_in[6];
    const float* gWhhb = (const float*)d_in[7];
    const float* gbihb = (const float*)d_in[8];
    const float* gbhhb = (const float*)d_in[9];
    const float* hW    = (const float*)d_in[10];
    const float* hb    = (const float*)d_in[11];
    const float* tW    = (const float*)d_in[12];
    const float* tb    = (const float*)d_in[13];
    const float* trans = (const float*)d_in[14];
    const float* lW    = (const float*)d_in[15];
    const float* lb    = (const float*)d_in[16];
    const int* masks   = (const int*)d_in[17];
    const int* lens    = (const int*)d_in[18];
    const int* labels  = (const int*)d_in[19];
    float* out = (float*)d_out;

    const int smem_gru = (96 * 260 + 16 * 260 + 16 * 36) * 4 + 16 * 4;
    cudaFuncSetAttribute(gru_v3, cudaFuncAttributeMaxDynamicSharedMemorySize, smem_gru);

    prep_all<<<NB_MAIN + NB_Z, 128>>>(sents, mtab, masks, lens, gWihf, gWihb);  // 1
    prep_small<<<33, 256>>>(hW, tW, hb, tb);                                     // 2
    gemm_gi_tf32<<<dim3(6, 128, 2), 128>>>(gbihf, gbihb);                        // 3
    gru_v3<<<128, 128, smem_gru>>>(lens, gWhhf, gWhhb, gbhhf, gbhhb);            // 4 <- ncu
    fk_kernel<<<1024, 256>>>();                                                  // 5
    crf_kernel<<<16, 128>>>(lens, trans);                                        // 6
    poolcls<<<B, 512>>>(lW, lb);                                                 // 7
    loss_kernel<<<1, 128>>>(labels, out);                                        // 8
}

// round 8
// speedup vs baseline: 4.6781x; 1.1634x over previous
#include <cuda_runtime.h>
#include <math.h>
#include <stdint.h>

constexpr int B   = 128;
constexpr int L   = 128;
constexpr int D   = 300;
constexpr int MD  = 50;
constexpr int GIN = 350;
constexpr int GINP= 352;
constexpr int HD  = 256;
constexpr int G3  = 768;
constexpr int H   = 512;
constexpr int R   = 128;
constexpr int T   = 4;
constexpr int NK  = 4;
constexpr int ML  = B * L;

// ---- static scratch ----
__device__ float d_x[ML * GINP];
__device__ float d_Wp[2 * G3 * GINP];
__device__ float d_gi[2 * (size_t)ML * G3];
__device__ float d_h[2 * 2 * B * HD];
__device__ float d_ctx[(size_t)ML * H];
__device__ float d_wtab[ML];
__device__ float d_Wc[16 * H];
__device__ float d_fk[NK * ML * T];
__device__ float d_alpha[NK * ML * T];
__device__ float d_sp[NK * ML];
__device__ float d_spsum[NK * B];
__device__ float d_tbeff[NK * T];
__device__ float d_scores[B * 3];
__device__ int   d_flags[2 * 8 * 128 * 8];   // [dir][bg][t][gs]

__device__ __forceinline__ float lse4(float v0, float v1, float v2, float v3) {
    float mx = fmaxf(fmaxf(v0, v1), fmaxf(v2, v3));
    return mx + logf(expf(v0 - mx) + expf(v1 - mx) + expf(v2 - mx) + expf(v3 - mx));
}
__device__ __forceinline__ float tf32r(float x) {
    uint32_t u; asm("cvt.rna.tf32.f32 %0, %1;" : "=r"(u) : "f"(x));
    return __uint_as_float(u);
}
__device__ __forceinline__ float tanha(float x) {
    float r; asm("tanh.approx.f32 %0, %1;" : "=f"(r) : "f"(x)); return r;
}
__device__ __forceinline__ float sigma(float x) {
    return fmaf(0.5f, tanha(0.5f * x), 0.5f);
}
__device__ __forceinline__ void mma8(float* c, const uint32_t* a, const uint32_t* b) {
    asm("mma.sync.aligned.m16n8k8.row.col.f32.tf32.tf32.f32 "
        "{%0,%1,%2,%3},{%4,%5,%6,%7},{%8,%9},{%0,%1,%2,%3};"
        : "+f"(c[0]), "+f"(c[1]), "+f"(c[2]), "+f"(c[3])
        : "r"(a[0]), "r"(a[1]), "r"(a[2]), "r"(a[3]), "r"(b[0]), "r"(b[1]));
}

// ---- prep_all ----
constexpr int NB_X = ML, NB_W = 2 * G3, NB_MAIN = NB_X + NB_W + 1;
constexpr int NB_Z = 2048;
constexpr size_t CTX4 = (size_t)ML * H / 4;
constexpr size_t H4   = 2 * B * HD / 4;
constexpr size_t FL4  = sizeof(d_flags) / 16;
constexpr size_t ZT   = CTX4 + H4 + FL4;

__global__ void prep_all(const float* __restrict__ sents, const float* __restrict__ mtab,
                         const int* __restrict__ masks, const int* __restrict__ lens,
                         const float* __restrict__ Wf, const float* __restrict__ Wb) {
    const int bid = blockIdx.x;
    if (bid < NB_X) {
        const int row = bid;
        const int msk = masks[row];
        for (int k = threadIdx.x; k < GINP; k += blockDim.x) {
            float v;
            if (k < D)        v = sents[(size_t)row * D + k];
            else if (k < GIN) v = mtab[msk * MD + (k - D)];
            else              v = 0.f;
            d_x[(size_t)row * GINP + k] = v;
        }
    } else if (bid < NB_X + NB_W) {
        const int q = bid - NB_X;
        const int dd = q / G3, g = q % G3;
        const float* W = dd ? Wb : Wf;
        for (int k = threadIdx.x; k < GINP; k += blockDim.x)
            d_Wp[((size_t)dd * G3 + g) * GINP + k] = (k < GIN) ? W[(size_t)g * GIN + k] : 0.f;
    } else if (bid == NB_X + NB_W) {
        const int b = threadIdx.x;
        if (b >= B) return;
        int begin = 0, tnum = 0; bool found = false;
        for (int j = 0; j < L; j++) {
            int m = masks[b * L + j];
            tnum += m;
            if (!found && m == 1) { begin = j; found = true; }
        }
        const int len = lens[b];
        const float lf = (float)len;
        for (int j = 0; j < L; j++) {
            float w = (j < begin) ? (1.f - (float)(begin - j) / lf) : 0.f;
            if (masks[b * L + j] == 1) w = 1.f;
            if (j > begin + tnum) w = 1.f - (float)(j - begin) / lf;
            if (j > len) w = 0.f;
            d_wtab[b * L + j] = w;
        }
    } else {
        const int z = bid - NB_MAIN;
        float4 zz = {0.f, 0.f, 0.f, 0.f};
        for (size_t i = (size_t)z * 128 + threadIdx.x; i < ZT; i += (size_t)NB_Z * 128) {
            if (i < CTX4)            ((float4*)d_ctx)[i] = zz;
            else if (i < CTX4 + H4)  ((float4*)d_h)[i - CTX4] = zz;
            else                     ((float4*)d_flags)[i - CTX4 - H4] = zz;
        }
    }
}

// ---- prep_small ----
__global__ void prep_small(const float* __restrict__ hW, const float* __restrict__ tW,
                           const float* __restrict__ hb, const float* __restrict__ tb) {
    if (blockIdx.x < 32) {
        const int idx = blockIdx.x * 256 + threadIdx.x;
        const int kb = idx >> 11, tt = (idx >> 9) & 3, h = idx & 511;
        float s = 0.f;
        for (int r = 0; r < R; r++)
            s += tW[(kb * T + tt) * R + r] * hW[((size_t)kb * R + r) * H + h];
        d_Wc[idx] = s;
    } else {
        const int i = threadIdx.x;
        if (i < NK * T) {
            const int kb = i >> 2;
            float s = tb[i];
            for (int r = 0; r < R; r++) s += hb[kb * R + r] * tW[i * R + r];
            d_tbeff[i] = s;
        }
    }
}

// ---- GEMM 1 (tf32, 256 threads): gi[dir][l*B+b][g] = x[b,l] @ Wp[dir]^T + bih ----
__global__ void __launch_bounds__(256) gemm_gi_tf32(const float* __restrict__ bihf,
                                                    const float* __restrict__ bihb) {
    __shared__ __align__(16) float a_s[128 * 20];
    __shared__ __align__(16) float b_s[128 * 20];
    const int tid = threadIdx.x;
    const int lane = tid & 31, warp = tid >> 5;
    const int n0 = blockIdx.x * 128;
    const int l  = blockIdx.y;
    const int dir = blockIdx.z;
    const int wm = (warp & 1) * 64, wn = (warp >> 1) * 32;
    const int lrow = tid >> 2, lc4 = (tid & 3) * 4;

    float acc[4][4][4];
#pragma unroll
    for (int i = 0; i < 4; i++)
#pragma unroll
        for (int j = 0; j < 4; j++)
#pragma unroll
            for (int q = 0; q < 4; q++) acc[i][j][q] = 0.f;

    for (int k0 = 0; k0 < GINP; k0 += 16) {
#pragma unroll
        for (int p = 0; p < 2; p++) {
            const int r = p * 64 + lrow;
            float4 va = *(const float4*)(d_x + ((size_t)r * L + l) * GINP + k0 + lc4);
            float4 vb = *(const float4*)(d_Wp + ((size_t)dir * G3 + n0 + r) * GINP + k0 + lc4);
            va.x = tf32r(va.x); va.y = tf32r(va.y); va.z = tf32r(va.z); va.w = tf32r(va.w);
            vb.x = tf32r(vb.x); vb.y = tf32r(vb.y); vb.z = tf32r(vb.z); vb.w = tf32r(vb.w);
            *(float4*)&a_s[r * 20 + lc4] = va;
            *(float4*)&b_s[r * 20 + lc4] = vb;
        }
        __syncthreads();
#pragma unroll
        for (int ks = 0; ks < 16; ks += 8) {
            uint32_t af[4][4], bf[4][2];
#pragma unroll
            for (int i = 0; i < 4; i++) {
                const int r0 = wm + i * 16 + (lane >> 2), cc = ks + (lane & 3);
                af[i][0] = __float_as_uint(a_s[r0 * 20 + cc]);
                af[i][1] = __float_as_uint(a_s[(r0 + 8) * 20 + cc]);
                af[i][2] = __float_as_uint(a_s[r0 * 20 + cc + 4]);
                af[i][3] = __float_as_uint(a_s[(r0 + 8) * 20 + cc + 4]);
            }
#pragma unroll
            for (int j = 0; j < 4; j++) {
                const int nn = wn + j * 8 + (lane >> 2), kk = ks + (lane & 3);
                bf[j][0] = __float_as_uint(b_s[nn * 20 + kk]);
                bf[j][1] = __float_as_uint(b_s[nn * 20 + kk + 4]);
            }
#pragma unroll
            for (int i = 0; i < 4; i++)
#pragma unroll
                for (int j = 0; j < 4; j++) mma8(acc[i][j], af[i], bf[j]);
        }
        __syncthreads();
    }
    const float* bih = dir ? bihb : bihf;
    float* C = d_gi + (size_t)dir * ML * G3 + (size_t)l * B * G3;
#pragma unroll
    for (int i = 0; i < 4; i++) {
        const int rb = wm + i * 16 + (lane >> 2);
#pragma unroll
        for (int j = 0; j < 4; j++) {
            const int nn = n0 + wn + j * 8 + 2 * (lane & 3);
            const float b0 = bih[nn], b1 = bih[nn + 1];
            float2 v0 = {acc[i][j][0] + b0, acc[i][j][1] + b1};
            float2 v1 = {acc[i][j][2] + b0, acc[i][j][3] + b1};
            *(float2*)(C + (size_t)rb * G3 + nn) = v0;
            *(float2*)(C + (size_t)(rb + 8) * G3 + nn) = v1;
        }
    }
}

// ---- gru_v4: 128 dataflow blocks, 256 threads, K-split across warp halves ----
__global__ void __launch_bounds__(256, 1) gru_v4(const int* __restrict__ lens,
                                                 const float* __restrict__ Whhf,
                                                 const float* __restrict__ Whhb,
                                                 const float* __restrict__ bhhf,
                                                 const float* __restrict__ bhhb) {
    extern __shared__ float sm[];
    float* w_s   = sm;                       // [96][260]
    float* a_s   = sm + 96 * 260;            // [16][260]
    float* hraw  = a_s + 16 * 260;           // [16][36]
    float* red   = hraw + 16 * 36;           // [128][13]
    int*   len_s = (int*)(red + 128 * 13);   // [16]

    const int tid = threadIdx.x;
    const int bx = blockIdx.x;
    const int dir = bx >> 6;
    const int gs  = (bx >> 3) & 7;
    const int bg  = bx & 7;
    const int b0  = bg * 16;
    const float* Whh = dir ? Whhb : Whhf;
    const float* bhh = dir ? bhhb : bhhf;

    for (int q = tid; q < 96 * 64; q += 256) {
        const int n = q >> 6, c4 = (q & 63) * 4;
        const int grow = (n >> 5) * HD + gs * 32 + (n & 31);
        float4 v = *(const float4*)(Whh + (size_t)grow * HD + c4);
        v.x = tf32r(v.x); v.y = tf32r(v.y); v.z = tf32r(v.z); v.w = tf32r(v.w);
        *(float4*)&w_s[n * 260 + c4] = v;
    }
    if (tid < 16) len_s[tid] = lens[b0 + tid];
    __syncthreads();

    const int lane = tid & 31, warp = tid >> 5;
    const int wlo = warp & 3, kh = warp >> 2;
    const int r0 = lane >> 2, cb = lane & 3;
    const int ul = wlo * 8 + 2 * cb;
    const int ug = gs * 32 + ul;
    const float bR0 = bhh[ug],        bR1 = bhh[ug + 1];
    const float bZ0 = bhh[256 + ug],  bZ1 = bhh[256 + ug + 1];
    const float bN0 = bhh[512 + ug],  bN1 = bhh[512 + ug + 1];
    const float* gi = d_gi + (size_t)dir * ML * G3;
    int* flg = d_flags + ((dir * 8 + bg) * 128) * 8;

    const int lenA = len_s[r0], lenB = len_s[r0 + 8];

    for (int t = 0; t < L; t++) {
        const int buf = t & 1;
        const float* hbase = d_h + buf * (2 * B * HD) + dir * (B * HD);
        float* hout = d_h + (buf ^ 1) * (2 * B * HD) + dir * (B * HD);

        // gi prefetch (warps 0-3 only)
        float2 gr[2], gz[2], gn[2];
        int posv[2]; bool act[2];
        if (warp < 4) {
            const int lenv[2] = {lenA, lenB};
#pragma unroll
            for (int s = 0; s < 2; s++) {
                act[s] = (t < lenv[s]);
                posv[s] = dir ? (lenv[s] - 1 - t) : t;
                if (act[s]) {
                    const float* gp = gi + ((size_t)posv[s] * B + (b0 + r0 + 8 * s)) * G3;
                    gr[s] = *(const float2*)(gp + ug);
                    gz[s] = *(const float2*)(gp + 256 + ug);
                    gn[s] = *(const float2*)(gp + 512 + ug);
                }
            }
        }

        float acc[3][4];
#pragma unroll
        for (int j = 0; j < 3; j++)
#pragma unroll
            for (int q = 0; q < 4; q++) acc[j][q] = 0.f;

        if (t > 0) {
            if (tid < 8) {
                volatile int* f = (volatile int*)(flg + (t - 1) * 8 + tid);
                while (*f == 0) {}
                __threadfence();
            }
            __syncthreads();
#pragma unroll
            for (int i = 0; i < 2; i++) {
                const int q = tid + 256 * i;          // 0..511
                const int r = q >> 5;
                const int ch = q & 31;
                const int c8 = ch * 8;
                float4 v0 = __ldcg((const float4*)(hbase + (size_t)(b0 + r) * HD + c8));
                float4 v1 = __ldcg((const float4*)(hbase + (size_t)(b0 + r) * HD + c8 + 4));
                if ((ch >> 2) == gs) {
                    const int off = c8 - gs * 32;
                    *(float4*)&hraw[r * 36 + off] = v0;
                    *(float4*)&hraw[r * 36 + off + 4] = v1;
                }
                v0.x = tf32r(v0.x); v0.y = tf32r(v0.y); v0.z = tf32r(v0.z); v0.w = tf32r(v0.w);
                v1.x = tf32r(v1.x); v1.y = tf32r(v1.y); v1.z = tf32r(v1.z); v1.w = tf32r(v1.w);
                *(float4*)&a_s[r * 260 + c8] = v0;
                *(float4*)&a_s[r * 260 + c8 + 4] = v1;
            }
            __syncthreads();

#pragma unroll 4
            for (int kk = 0; kk < 16; kk++) {
                const int cc = kh * 128 + kk * 8 + cb;
                uint32_t a[4];
                a[0] = __float_as_uint(a_s[r0 * 260 + cc]);
                a[1] = __float_as_uint(a_s[(r0 + 8) * 260 + cc]);
                a[2] = __float_as_uint(a_s[r0 * 260 + cc + 4]);
                a[3] = __float_as_uint(a_s[(r0 + 8) * 260 + cc + 4]);
#pragma unroll
                for (int j = 0; j < 3; j++) {
                    const int nn = j * 32 + wlo * 8 + r0;
                    uint32_t bb[2];
                    bb[0] = __float_as_uint(w_s[nn * 260 + cc]);
                    bb[1] = __float_as_uint(w_s[nn * 260 + cc + 4]);
                    mma8(acc[j], a, bb);
                }
            }
        }

        // reduce the two k-halves
        if (warp >= 4) {
            const int idx = (warp - 4) * 32 + lane;
#pragma unroll
            for (int j = 0; j < 3; j++)
#pragma unroll
                for (int q = 0; q < 4; q++) red[idx * 13 + j * 4 + q] = acc[j][q];
        }
        __syncthreads();

        if (warp < 4) {
            const int idx = warp * 32 + lane;
#pragma unroll
            for (int j = 0; j < 3; j++)
#pragma unroll
                for (int q = 0; q < 4; q++) acc[j][q] += red[idx * 13 + j * 4 + q];

#pragma unroll
            for (int s = 0; s < 2; s++) {
                const int r = r0 + 8 * s;
                const int b = b0 + r;
                float2 hp;
                if (t > 0) hp = *(const float2*)&hraw[r * 36 + ul];
                else { hp.x = 0.f; hp.y = 0.f; }
                float2 hn = hp;
                if (act[s]) {
                    const float rrx = sigma(gr[s].x + acc[0][2 * s]     + bR0);
                    const float rry = sigma(gr[s].y + acc[0][2 * s + 1] + bR1);
                    const float zzx = sigma(gz[s].x + acc[1][2 * s]     + bZ0);
                    const float zzy = sigma(gz[s].y + acc[1][2 * s + 1] + bZ1);
                    const float nnx = tanha(gn[s].x + rrx * (acc[2][2 * s]     + bN0));
                    const float nny = tanha(gn[s].y + rry * (acc[2][2 * s + 1] + bN1));
                    hn.x = (1.f - zzx) * nnx + zzx * hp.x;
                    hn.y = (1.f - zzy) * nny + zzy * hp.y;
                    const int pos = posv[s];
                    const float wt = d_wtab[b * L + pos];
                    float2 cv = {hn.x * wt, hn.y * wt};
                    *(float2*)(d_ctx + ((size_t)b * L + pos) * H + dir * HD + ug) = cv;
                }
                *(float2*)(hout + (size_t)b * HD + ug) = hn;
            }
        }

        __syncthreads();
        if (tid == 0) {
            __threadfence();
            *(volatile int*)(flg + t * 8 + gs) = 1;
        }
    }
}

// ---- fk2 (tiled): fk = ctx @ Wc^T + tbeff, ctx read once ----
__global__ void __launch_bounds__(256) fk2() {
    extern __shared__ float fsm[];
    float* wc_s = fsm;              // [16][516]
    float* ct_s = fsm + 16 * 516;   // [16][520]
    const int tid = threadIdx.x;
    const int m0 = blockIdx.x * 128;

    for (int q = tid; q < 2048; q += 256) {
        const int o = q >> 7, c4 = (q & 127) * 4;
        *(float4*)&wc_s[o * 516 + c4] = *(const float4*)(d_Wc + (size_t)o * H + c4);
    }
    __syncthreads();

    const int ml = tid >> 4, o = tid & 15;
    const float tbe = d_tbeff[o];
    for (int c = 0; c < 8; c++) {
        for (int q = tid; q < 2048; q += 256) {
            const int r = q >> 7, c4 = (q & 127) * 4;
            *(float4*)&ct_s[r * 520 + c4] =
                *(const float4*)(d_ctx + (size_t)(m0 + c * 16 + r) * H + c4);
        }
        __syncthreads();
        float acc = 0.f;
#pragma unroll 8
        for (int k4 = 0; k4 < 128; k4++) {
            float4 cv = *(const float4*)&ct_s[ml * 520 + k4 * 4];
            float4 wv = *(const float4*)&wc_s[o * 516 + k4 * 4];
            acc += cv.x * wv.x + cv.y * wv.y + cv.z * wv.z + cv.w * wv.w;
        }
        const int m = m0 + c * 16 + ml;
        d_fk[((size_t)(o >> 2) * ML + m) * T + (o & 3)] = acc + tbe;
        __syncthreads();
    }
}

// ---- CRF forward-backward marginals ----
__global__ void __launch_bounds__(128) crf_kernel(const int* __restrict__ lens,
                                                  const float* __restrict__ trans) {
    const int tid = threadIdx.x;
    const int tag = tid & 3;
    const int chain = blockIdx.x * 32 + (tid >> 2);
    const int kb = chain >> 7;
    const int b  = chain & 127;
    const int len = lens[b];
    const unsigned fm = 0xffffffffu;
    const int base = (tid & 31) & ~3;

    float tcol[4], trow[4];
#pragma unroll
    for (int i = 0; i < 4; i++) {
        tcol[i] = trans[kb * 16 + i * 4 + tag];
        trow[i] = trans[kb * 16 + tag * 4 + i];
    }
    const float* f = d_fk + ((size_t)kb * ML + (size_t)b * L) * T;
    float* al = d_alpha + ((size_t)kb * ML + (size_t)b * L) * T;

    float alpha = f[tag];
    al[tag] = alpha;
    for (int l = 1; l < L; l++) {
        float a0 = __shfl_sync(fm, alpha, base + 0);
        float a1 = __shfl_sync(fm, alpha, base + 1);
        float a2 = __shfl_sync(fm, alpha, base + 2);
        float a3 = __shfl_sync(fm, alpha, base + 3);
        float na = lse4(a0 + tcol[0], a1 + tcol[1], a2 + tcol[2], a3 + tcol[3]) + f[l * T + tag];
        if (l < len) alpha = na;
        al[l * T + tag] = alpha;
    }
    float beta = 0.f, ssum = 0.f;
    float* sp = d_sp + (size_t)(kb * B + b) * L;
    for (int l = L - 1; l >= 0; l--) {
        float v = al[l * T + tag] + beta;
        float v0 = __shfl_sync(fm, v, base + 0);
        float v1 = __shfl_sync(fm, v, base + 1);
        float v2 = __shfl_sync(fm, v, base + 2);
        float v3 = __shfl_sync(fm, v, base + 3);
        float p1 = expf(v1 - lse4(v0, v1, v2, v3));
        float spl = (l < len) ? p1 : 0.f;
        ssum += spl;
        if (tag == 0) sp[l] = spl;
        if (l >= 1) {
            float fb = f[l * T + tag] + beta;
            float c0 = __shfl_sync(fm, fb, base + 0);
            float c1 = __shfl_sync(fm, fb, base + 1);
            float c2 = __shfl_sync(fm, fb, base + 2);
            float c3 = __shfl_sync(fm, fb, base + 3);
            float nb2 = lse4(trow[0] + c0, trow[1] + c1, trow[2] + c2, trow[3] + c3);
            if (l < len) beta = nb2;
        }
    }
    if (tag == 0) d_spsum[kb * B + b] = ssum;
}

// ---- pooling + classifier fused ----
__global__ void __launch_bounds__(512) poolcls(const float* __restrict__ lW,
                                               const float* __restrict__ lb) {
    const int b = blockIdx.x, tid = threadIdx.x;
    __shared__ float spn[512];
    __shared__ float red[3][512];
    {
        const int kb = tid >> 7, l = tid & 127;
        spn[tid] = d_sp[(size_t)(kb * B + b) * L + l] / d_spsum[kb * B + b];
    }
    __syncthreads();
    float a0 = 0.f, a1 = 0.f, a2 = 0.f, a3 = 0.f;
    const float* c = d_ctx + (size_t)b * L * H + tid;
    for (int l = 0; l < 128; l++) {
        float cv = c[(size_t)l * H];
        a0 += spn[l] * cv; a1 += spn[128 + l] * cv;
        a2 += spn[256 + l] * cv; a3 += spn[384 + l] * cv;
    }
    float p0 = 0.f, p1 = 0.f, p2 = 0.f, s;
    s = fmaxf(a0, 0.f); p0 += s * lW[tid];        p1 += s * lW[2048 + tid];        p2 += s * lW[4096 + tid];
    s = fmaxf(a1, 0.f); p0 += s * lW[512 + tid];  p1 += s * lW[2560 + tid];        p2 += s * lW[4608 + tid];
    s = fmaxf(a2, 0.f); p0 += s * lW[1024 + tid]; p1 += s * lW[3072 + tid];        p2 += s * lW[5120 + tid];
    s = fmaxf(a3, 0.f); p0 += s * lW[1536 + tid]; p1 += s * lW[3584 + tid];        p2 += s * lW[5632 + tid];
    red[0][tid] = p0; red[1][tid] = p1; red[2][tid] = p2;
    __syncthreads();
    for (int off = 256; off > 0; off >>= 1) {
        if (tid < off) {
            red[0][tid] += red[0][tid + off];
            red[1][tid] += red[1][tid + off];
            red[2][tid] += red[2][tid + off];
        }
        __syncthreads();
    }
    if (tid < 3) d_scores[b * 3 + tid] = red[tid][0] + lb[tid];
}

__global__ void __launch_bounds__(128) loss_kernel(const int* __restrict__ labels,
                                                   float* __restrict__ out) {
    __shared__ float red[128];
    const int b = threadIdx.x;
    float s0 = d_scores[b * 3], s1 = d_scores[b * 3 + 1], s2 = d_scores[b * 3 + 2];
    float m = fmaxf(s0, fmaxf(s1, s2));
    float lse = m + logf(expf(s0 - m) + expf(s1 - m) + expf(s2 - m));
    int lab = labels[b];
    float sl = (lab == 0) ? s0 : ((lab == 1) ? s1 : s2);
    red[b] = lse - sl;
    __syncthreads();
    for (int off = 64; off > 0; off >>= 1) {
        if (b < off) red[b] += red[b + off];
        __syncthreads();
    }
    if (b == 0) out[0] = red[0] / (float)B;
}

extern "C" void kernel_launch(void* const* d_in, const int* in_sizes, int n_in,
                              void* d_out, int out_size) {
    (void)in_sizes; (void)n_in; (void)out_size;
    const float* sents = (const float*)d_in[0];
    const float* mtab  = (const float*)d_in[1];
    const float* gWihf = (const float*)d_in[2];
    const float* gWhhf = (const float*)d_in[3];
    const float* gbihf = (const float*)d_in[4];
    const float* gbhhf = (const float*)d_in[5];
    const float* gWihb = (const float*)d_in[6];
    const float* gWhhb = (const float*)d_in[7];
    const float* gbihb = (const float*)d_in[8];
    const float* gbhhb = (const float*)d_in[9];
    const float* hW    = (const float*)d_in[10];
    const float* hb    = (const float*)d_in[11];
    const float* tW    = (const float*)d_in[12];
    const float* tb    = (const float*)d_in[13];
    const float* trans = (const float*)d_in[14];
    const float* lW    = (const float*)d_in[15];
    const float* lb    = (const float*)d_in[16];
    const int* masks   = (const int*)d_in[17];
    const int* lens    = (const int*)d_in[18];
    const int* labels  = (const int*)d_in[19];
    float* out = (float*)d_out;

    const int smem_gru = (96 * 260 + 16 * 260 + 16 * 36 + 128 * 13) * 4 + 16 * 4;
    cudaFuncSetAttribute(gru_v4, cudaFuncAttributeMaxDynamicSharedMemorySize, smem_gru);
    const int smem_fk = (16 * 516 + 16 * 520) * 4;
    cudaFuncSetAttribute(fk2, cudaFuncAttributeMaxDynamicSharedMemorySize, smem_fk);

    prep_all<<<NB_MAIN + NB_Z, 128>>>(sents, mtab, masks, lens, gWihf, gWihb);  // 1
    prep_small<<<33, 256>>>(hW, tW, hb, tb);                                     // 2
    gemm_gi_tf32<<<dim3(6, 128, 2), 256>>>(gbihf, gbihb);                        // 3
    gru_v4<<<128, 256, smem_gru>>>(lens, gWhhf, gWhhb, gbhhf, gbhhb);            // 4 <- ncu
    fk2<<<128, 256, smem_fk>>>();                                                // 5
    crf_kernel<<<16, 128>>>(lens, trans);                                        // 6
    poolcls<<<B, 512>>>(lW, lb);                                                 // 7
    loss_kernel<<<1, 128>>>(labels, out);                                        // 8
}

// round 9
// speedup vs baseline: 4.7286x; 1.0108x over previous
#include <cuda_runtime.h>
#include <cuda_bf16.h>
#include <math.h>
#include <stdint.h>

constexpr int B   = 128;
constexpr int L   = 128;
constexpr int D   = 300;
constexpr int MD  = 50;
constexpr int GIN = 350;
constexpr int GINP= 352;
constexpr int HD  = 256;
constexpr int G3  = 768;
constexpr int H   = 512;
constexpr int R   = 128;
constexpr int T   = 4;
constexpr int NK  = 4;
constexpr int ML  = B * L;

// ---- static scratch ----
__device__ __align__(16) __nv_bfloat16 d_xh[ML * GINP];
__device__ __align__(16) __nv_bfloat16 d_Wph[2 * G3 * GINP];
__device__ float d_gi[2 * (size_t)ML * G3];
__device__ float d_h[2 * 2 * B * HD];
__device__ float d_ctx[(size_t)ML * H];
__device__ float d_wtab[ML];
__device__ float d_Wc[16 * H];
__device__ float d_fk[NK * ML * T];
__device__ float d_sp[NK * ML];
__device__ float d_spsum[NK * B];
__device__ float d_tbeff[NK * T];
__device__ float d_scores[B * 3];
__device__ int   d_flags[2 * 8 * 128 * 8];   // [dir][bg][t][gs]

__device__ __forceinline__ float lse4(float v0, float v1, float v2, float v3) {
    float mx = fmaxf(fmaxf(v0, v1), fmaxf(v2, v3));
    return mx + logf(expf(v0 - mx) + expf(v1 - mx) + expf(v2 - mx) + expf(v3 - mx));
}
__device__ __forceinline__ float tf32r(float x) {
    uint32_t u; asm("cvt.rna.tf32.f32 %0, %1;" : "=r"(u) : "f"(x));
    return __uint_as_float(u);
}
__device__ __forceinline__ float tanha(float x) {
    float r; asm("tanh.approx.f32 %0, %1;" : "=f"(r) : "f"(x)); return r;
}
__device__ __forceinline__ float sigma(float x) {
    return fmaf(0.5f, tanha(0.5f * x), 0.5f);
}
__device__ __forceinline__ void mma8(float* c, const uint32_t* a, const uint32_t* b) {
    asm("mma.sync.aligned.m16n8k8.row.col.f32.tf32.tf32.f32 "
        "{%0,%1,%2,%3},{%4,%5,%6,%7},{%8,%9},{%0,%1,%2,%3};"
        : "+f"(c[0]), "+f"(c[1]), "+f"(c[2]), "+f"(c[3])
        : "r"(a[0]), "r"(a[1]), "r"(a[2]), "r"(a[3]), "r"(b[0]), "r"(b[1]));
}
__device__ __forceinline__ void mma16(float* c, const uint32_t* a, const uint32_t* b) {
    asm("mma.sync.aligned.m16n8k16.row.col.f32.bf16.bf16.f32 "
        "{%0,%1,%2,%3},{%4,%5,%6,%7},{%8,%9},{%0,%1,%2,%3};"
        : "+f"(c[0]), "+f"(c[1]), "+f"(c[2]), "+f"(c[3])
        : "r"(a[0]), "r"(a[1]), "r"(a[2]), "r"(a[3]), "r"(b[0]), "r"(b[1]));
}

// ---- prep_all ----
constexpr int NB_X = ML, NB_W = 2 * G3, NB_MAIN = NB_X + NB_W + 1;
constexpr int NB_Z = 2048;
constexpr size_t CTX4 = (size_t)ML * H / 4;
constexpr size_t H4   = 2 * B * HD / 4;
constexpr size_t FL4  = sizeof(d_flags) / 16;
constexpr size_t ZT   = CTX4 + H4 + FL4;

__global__ void prep_all(const float* __restrict__ sents, const float* __restrict__ mtab,
                         const int* __restrict__ masks, const int* __restrict__ lens,
                         const float* __restrict__ Wf, const float* __restrict__ Wb) {
    const int bid = blockIdx.x;
    if (bid < NB_X) {
        const int row = bid;
        const int msk = masks[row];
        for (int k = threadIdx.x; k < GINP; k += blockDim.x) {
            float v;
            if (k < D)        v = sents[(size_t)row * D + k];
            else if (k < GIN) v = mtab[msk * MD + (k - D)];
            else              v = 0.f;
            d_xh[(size_t)row * GINP + k] = __float2bfloat16(v);
        }
    } else if (bid < NB_X + NB_W) {
        const int q = bid - NB_X;
        const int dd = q / G3, g = q % G3;
        const float* W = dd ? Wb : Wf;
        for (int k = threadIdx.x; k < GINP; k += blockDim.x)
            d_Wph[((size_t)dd * G3 + g) * GINP + k] =
                __float2bfloat16((k < GIN) ? W[(size_t)g * GIN + k] : 0.f);
    } else if (bid == NB_X + NB_W) {
        const int b = threadIdx.x;
        if (b >= B) return;
        int begin = 0, tnum = 0; bool found = false;
        for (int j = 0; j < L; j++) {
            int m = masks[b * L + j];
            tnum += m;
            if (!found && m == 1) { begin = j; found = true; }
        }
        const int len = lens[b];
        const float lf = (float)len;
        for (int j = 0; j < L; j++) {
            float w = (j < begin) ? (1.f - (float)(begin - j) / lf) : 0.f;
            if (masks[b * L + j] == 1) w = 1.f;
            if (j > begin + tnum) w = 1.f - (float)(j - begin) / lf;
            if (j > len) w = 0.f;
            d_wtab[b * L + j] = w;
        }
    } else {
        const int z = bid - NB_MAIN;
        float4 zz = {0.f, 0.f, 0.f, 0.f};
        for (size_t i = (size_t)z * 128 + threadIdx.x; i < ZT; i += (size_t)NB_Z * 128) {
            if (i < CTX4)            ((float4*)d_ctx)[i] = zz;
            else if (i < CTX4 + H4)  ((float4*)d_h)[i - CTX4] = zz;
            else                     ((float4*)d_flags)[i - CTX4 - H4] = zz;
        }
    }
}

// ---- prep_small ----
__global__ void prep_small(const float* __restrict__ hW, const float* __restrict__ tW,
                           const float* __restrict__ hb, const float* __restrict__ tb) {
    if (blockIdx.x < 32) {
        const int idx = blockIdx.x * 256 + threadIdx.x;
        const int kb = idx >> 11, tt = (idx >> 9) & 3, h = idx & 511;
        float s = 0.f;
        for (int r = 0; r < R; r++)
            s += tW[(kb * T + tt) * R + r] * hW[((size_t)kb * R + r) * H + h];
        d_Wc[idx] = s;
    } else {
        const int i = threadIdx.x;
        if (i < NK * T) {
            const int kb = i >> 2;
            float s = tb[i];
            for (int r = 0; r < R; r++) s += hb[kb * R + r] * tW[i * R + r];
            d_tbeff[i] = s;
        }
    }
}

// ---- GEMM 1 (bf16 m16n8k16): gi[dir][l*B+b][g] = x[b,l] @ Wp[dir]^T + bih ----
__global__ void __launch_bounds__(256) gemm_gi_bf16(const float* __restrict__ bihf,
                                                    const float* __restrict__ bihb) {
    __shared__ __align__(16) uint32_t a_s[128 * 12];  // 8 used cols (bf16 pairs), pad 12
    __shared__ __align__(16) uint32_t b_s[128 * 12];
    const int tid = threadIdx.x;
    const int lane = tid & 31, warp = tid >> 5;
    const int n0 = blockIdx.x * 128;
    const int l  = blockIdx.y;
    const int dir = blockIdx.z;
    const int wm = (warp & 1) * 64, wn = (warp >> 1) * 32;
    const int lrow = tid >> 1, lhalf = tid & 1;   // load: row, 8-bf16 half

    float acc[4][4][4];
#pragma unroll
    for (int i = 0; i < 4; i++)
#pragma unroll
        for (int j = 0; j < 4; j++)
#pragma unroll
            for (int q = 0; q < 4; q++) acc[i][j][q] = 0.f;

    const int kb = lane & 3, rq = lane >> 2;
    for (int k0 = 0; k0 < GINP; k0 += 16) {
        uint4 va = *(const uint4*)(d_xh + ((size_t)lrow * L + l) * GINP + k0 + lhalf * 8);
        uint4 vb = *(const uint4*)(d_Wph + ((size_t)dir * G3 + n0 + lrow) * GINP + k0 + lhalf * 8);
        *(uint4*)&a_s[lrow * 12 + lhalf * 4] = va;
        *(uint4*)&b_s[lrow * 12 + lhalf * 4] = vb;
        __syncthreads();
        uint32_t af[4][4], bf[4][2];
#pragma unroll
        for (int i = 0; i < 4; i++) {
            const int r0 = wm + i * 16 + rq;
            af[i][0] = a_s[r0 * 12 + kb];
            af[i][1] = a_s[(r0 + 8) * 12 + kb];
            af[i][2] = a_s[r0 * 12 + kb + 4];
            af[i][3] = a_s[(r0 + 8) * 12 + kb + 4];
        }
#pragma unroll
        for (int j = 0; j < 4; j++) {
            const int nn = wn + j * 8 + rq;
            bf[j][0] = b_s[nn * 12 + kb];
            bf[j][1] = b_s[nn * 12 + kb + 4];
        }
#pragma unroll
        for (int i = 0; i < 4; i++)
#pragma unroll
            for (int j = 0; j < 4; j++) mma16(acc[i][j], af[i], bf[j]);
        __syncthreads();
    }
    const float* bih = dir ? bihb : bihf;
    float* C = d_gi + (size_t)dir * ML * G3 + (size_t)l * B * G3;
#pragma unroll
    for (int i = 0; i < 4; i++) {
        const int rb = wm + i * 16 + rq;
#pragma unroll
        for (int j = 0; j < 4; j++) {
            const int nn = n0 + wn + j * 8 + 2 * kb;
            const float b0 = bih[nn], b1 = bih[nn + 1];
            float2 v0 = {acc[i][j][0] + b0, acc[i][j][1] + b1};
            float2 v1 = {acc[i][j][2] + b0, acc[i][j][3] + b1};
            *(float2*)(C + (size_t)rb * G3 + nn) = v0;
            *(float2*)(C + (size_t)(rb + 8) * G3 + nn) = v1;
        }
    }
}

// ---- gru_v5: per-warp slice poll + load overlap; K-split mma ----
__global__ void __launch_bounds__(256, 1) gru_v5(const int* __restrict__ lens,
                                                 const float* __restrict__ Whhf,
                                                 const float* __restrict__ Whhb,
                                                 const float* __restrict__ bhhf,
                                                 const float* __restrict__ bhhb) {
    extern __shared__ float sm[];
    float* w_s   = sm;                       // [96][260]
    float* a_s   = sm + 96 * 260;            // [16][260]
    float* hraw  = a_s + 16 * 260;           // [16][36]
    float* red   = hraw + 16 * 36;           // [128][13]
    int*   len_s = (int*)(red + 128 * 13);   // [16]

    const int tid = threadIdx.x;
    const int bx = blockIdx.x;
    const int dir = bx >> 6;
    const int gs  = (bx >> 3) & 7;
    const int bg  = bx & 7;
    const int b0  = bg * 16;
    const float* Whh = dir ? Whhb : Whhf;
    const float* bhh = dir ? bhhb : bhhf;

    for (int q = tid; q < 96 * 64; q += 256) {
        const int n = q >> 6, c4 = (q & 63) * 4;
        const int grow = (n >> 5) * HD + gs * 32 + (n & 31);
        float4 v = *(const float4*)(Whh + (size_t)grow * HD + c4);
        v.x = tf32r(v.x); v.y = tf32r(v.y); v.z = tf32r(v.z); v.w = tf32r(v.w);
        *(float4*)&w_s[n * 260 + c4] = v;
    }
    if (tid < 16) len_s[tid] = lens[b0 + tid];
    __syncthreads();

    const int lane = tid & 31, warp = tid >> 5;
    const int wlo = warp & 3, kh = warp >> 2;
    const int r0 = lane >> 2, cb = lane & 3;
    const int ul = wlo * 8 + 2 * cb;
    const int ug = gs * 32 + ul;
    const float bR0 = bhh[ug],        bR1 = bhh[ug + 1];
    const float bZ0 = bhh[256 + ug],  bZ1 = bhh[256 + ug + 1];
    const float bN0 = bhh[512 + ug],  bN1 = bhh[512 + ug + 1];
    const float* gi = d_gi + (size_t)dir * ML * G3;
    int* flg = d_flags + ((dir * 8 + bg) * 128) * 8;

    const int lenA = len_s[r0], lenB = len_s[r0 + 8];

    for (int t = 0; t < L; t++) {
        const int buf = t & 1;
        const float* hbase = d_h + buf * (2 * B * HD) + dir * (B * HD);
        float* hout = d_h + (buf ^ 1) * (2 * B * HD) + dir * (B * HD);

        // gi prefetch (warps 0-3 only) — independent of flags/h
        float2 gr[2], gz[2], gn[2];
        int posv[2]; bool act[2];
        if (warp < 4) {
            const int lenv[2] = {lenA, lenB};
#pragma unroll
            for (int s = 0; s < 2; s++) {
                act[s] = (t < lenv[s]);
                posv[s] = dir ? (lenv[s] - 1 - t) : t;
                if (act[s]) {
                    const float* gp = gi + ((size_t)posv[s] * B + (b0 + r0 + 8 * s)) * G3;
                    gr[s] = *(const float2*)(gp + ug);
                    gz[s] = *(const float2*)(gp + 256 + ug);
                    gn[s] = *(const float2*)(gp + 512 + ug);
                }
            }
        }

        float acc[3][4];
#pragma unroll
        for (int j = 0; j < 3; j++)
#pragma unroll
            for (int q = 0; q < 4; q++) acc[j][q] = 0.f;

        if (t > 0) {
            // warp w: wait for producer slice w, then load its 32 columns
            int fv;
            do {
                asm volatile("ld.acquire.gpu.global.b32 %0, [%1];"
                             : "=r"(fv) : "l"(flg + (t - 1) * 8 + warp));
            } while (fv == 0);
#pragma unroll
            for (int i = 0; i < 2; i++) {
                const int q = lane + 32 * i;          // 0..63
                const int r = q & 15;
                const int c8 = warp * 32 + (q >> 4) * 8;
                float4 v0 = __ldcg((const float4*)(hbase + (size_t)(b0 + r) * HD + c8));
                float4 v1 = __ldcg((const float4*)(hbase + (size_t)(b0 + r) * HD + c8 + 4));
                if (warp == gs) {
                    const int off = c8 - gs * 32;
                    *(float4*)&hraw[r * 36 + off] = v0;
                    *(float4*)&hraw[r * 36 + off + 4] = v1;
                }
                v0.x = tf32r(v0.x); v0.y = tf32r(v0.y); v0.z = tf32r(v0.z); v0.w = tf32r(v0.w);
                v1.x = tf32r(v1.x); v1.y = tf32r(v1.y); v1.z = tf32r(v1.z); v1.w = tf32r(v1.w);
                *(float4*)&a_s[r * 260 + c8] = v0;
                *(float4*)&a_s[r * 260 + c8 + 4] = v1;
            }
            __syncthreads();

#pragma unroll 4
            for (int kk = 0; kk < 16; kk++) {
                const int cc = kh * 128 + kk * 8 + cb;
                uint32_t a[4];
                a[0] = __float_as_uint(a_s[r0 * 260 + cc]);
                a[1] = __float_as_uint(a_s[(r0 + 8) * 260 + cc]);
                a[2] = __float_as_uint(a_s[r0 * 260 + cc + 4]);
                a[3] = __float_as_uint(a_s[(r0 + 8) * 260 + cc + 4]);
#pragma unroll
                for (int j = 0; j < 3; j++) {
                    const int nn = j * 32 + wlo * 8 + r0;
                    uint32_t bb[2];
                    bb[0] = __float_as_uint(w_s[nn * 260 + cc]);
                    bb[1] = __float_as_uint(w_s[nn * 260 + cc + 4]);
                    mma8(acc[j], a, bb);
                }
            }
        }

        // reduce k-halves
        if (warp >= 4) {
            const int idx = (warp - 4) * 32 + lane;
#pragma unroll
            for (int j = 0; j < 3; j++)
#pragma unroll
                for (int q = 0; q < 4; q++) red[idx * 13 + j * 4 + q] = acc[j][q];
        }
        __syncthreads();

        if (warp < 4) {
            const int idx = warp * 32 + lane;
#pragma unroll
            for (int j = 0; j < 3; j++)
#pragma unroll
                for (int q = 0; q < 4; q++) acc[j][q] += red[idx * 13 + j * 4 + q];

#pragma unroll
            for (int s = 0; s < 2; s++) {
                const int r = r0 + 8 * s;
                const int b = b0 + r;
                float2 hp;
                if (t > 0) hp = *(const float2*)&hraw[r * 36 + ul];
                else { hp.x = 0.f; hp.y = 0.f; }
                float2 hn = hp;
                if (act[s]) {
                    const float rrx = sigma(gr[s].x + acc[0][2 * s]     + bR0);
                    const float rry = sigma(gr[s].y + acc[0][2 * s + 1] + bR1);
                    const float zzx = sigma(gz[s].x + acc[1][2 * s]     + bZ0);
                    const float zzy = sigma(gz[s].y + acc[1][2 * s + 1] + bZ1);
                    const float nnx = tanha(gn[s].x + rrx * (acc[2][2 * s]     + bN0));
                    const float nny = tanha(gn[s].y + rry * (acc[2][2 * s + 1] + bN1));
                    hn.x = (1.f - zzx) * nnx + zzx * hp.x;
                    hn.y = (1.f - zzy) * nny + zzy * hp.y;
                    const int pos = posv[s];
                    const float wt = d_wtab[b * L + pos];
                    float2 cv = {hn.x * wt, hn.y * wt};
                    *(float2*)(d_ctx + ((size_t)b * L + pos) * H + dir * HD + ug) = cv;
                }
                *(float2*)(hout + (size_t)b * HD + ug) = hn;
            }
        }

        __syncthreads();
        if (tid == 0) {
            __threadfence();
            *(volatile int*)(flg + t * 8 + gs) = 1;
        }
    }
}

// ---- fk2 (tiled): fk = ctx @ Wc^T + tbeff ----
__global__ void __launch_bounds__(256) fk2() {
    extern __shared__ float fsm[];
    float* wc_s = fsm;              // [16][516]
    float* ct_s = fsm + 16 * 516;   // [16][520]
    const int tid = threadIdx.x;
    const int m0 = blockIdx.x * 128;

    for (int q = tid; q < 2048; q += 256) {
        const int o = q >> 7, c4 = (q & 127) * 4;
        *(float4*)&wc_s[o * 516 + c4] = *(const float4*)(d_Wc + (size_t)o * H + c4);
    }
    __syncthreads();

    const int ml = tid >> 4, o = tid & 15;
    const float tbe = d_tbeff[o];
    for (int c = 0; c < 8; c++) {
        for (int q = tid; q < 2048; q += 256) {
            const int r = q >> 7, c4 = (q & 127) * 4;
            *(float4*)&ct_s[r * 520 + c4] =
                *(const float4*)(d_ctx + (size_t)(m0 + c * 16 + r) * H + c4);
        }
        __syncthreads();
        float acc = 0.f;
#pragma unroll 8
        for (int k4 = 0; k4 < 128; k4++) {
            float4 cv = *(const float4*)&ct_s[ml * 520 + k4 * 4];
            float4 wv = *(const float4*)&wc_s[o * 516 + k4 * 4];
            acc += cv.x * wv.x + cv.y * wv.y + cv.z * wv.z + cv.w * wv.w;
        }
        const int m = m0 + c * 16 + ml;
        d_fk[((size_t)(o >> 2) * ML + m) * T + (o & 3)] = acc + tbe;
        __syncthreads();
    }
}

// ---- CRF marginals: 64 blocks x 32 threads, alpha in smem ----
__global__ void __launch_bounds__(32) crf_kernel(const int* __restrict__ lens,
                                                 const float* __restrict__ trans) {
    __shared__ float al_s[8 * 516];            // 8 chains x (128*4 + pad 4)
    const int tid = threadIdx.x;
    const int tag = tid & 3;
    const int ci  = tid >> 2;                  // chain in block 0..7
    const int chain = blockIdx.x * 8 + ci;
    const int kb = chain >> 7;
    const int b  = chain & 127;
    const int len = lens[b];
    const unsigned fm = 0xffffffffu;
    const int base = tid & ~3;
    float* al = al_s + ci * 516;

    float tcol[4], trow[4];
#pragma unroll
    for (int i = 0; i < 4; i++) {
        tcol[i] = trans[kb * 16 + i * 4 + tag];
        trow[i] = trans[kb * 16 + tag * 4 + i];
    }
    const float* f = d_fk + ((size_t)kb * ML + (size_t)b * L) * T;

    float alpha = f[tag];
    al[tag] = alpha;
    for (int l = 1; l < L; l++) {
        float a0 = __shfl_sync(fm, alpha, base + 0);
        float a1 = __shfl_sync(fm, alpha, base + 1);
        float a2 = __shfl_sync(fm, alpha, base + 2);
        float a3 = __shfl_sync(fm, alpha, base + 3);
        float na = lse4(a0 + tcol[0], a1 + tcol[1], a2 + tcol[2], a3 + tcol[3]) + f[l * T + tag];
        if (l < len) alpha = na;
        al[l * 4 + tag] = alpha;
    }
    float beta = 0.f, ssum = 0.f;
    float* sp = d_sp + (size_t)(kb * B + b) * L;
    for (int l = L - 1; l >= 0; l--) {
        float v = al[l * 4 + tag] + beta;
        float v0 = __shfl_sync(fm, v, base + 0);
        float v1 = __shfl_sync(fm, v, base + 1);
        float v2 = __shfl_sync(fm, v, base + 2);
        float v3 = __shfl_sync(fm, v, base + 3);
        float p1 = expf(v1 - lse4(v0, v1, v2, v3));
        float spl = (l < len) ? p1 : 0.f;
        ssum += spl;
        if (tag == 0) sp[l] = spl;
        if (l >= 1) {
            float fb = f[l * T + tag] + beta;
            float c0 = __shfl_sync(fm, fb, base + 0);
            float c1 = __shfl_sync(fm, fb, base + 1);
            float c2 = __shfl_sync(fm, fb, base + 2);
            float c3 = __shfl_sync(fm, fb, base + 3);
            float nb2 = lse4(trow[0] + c0, trow[1] + c1, trow[2] + c2, trow[3] + c3);
            if (l < len) beta = nb2;
        }
    }
    if (tag == 0) d_spsum[kb * B + b] = ssum;
}

// ---- pooling + classifier fused ----
__global__ void __launch_bounds__(512) poolcls(const float* __restrict__ lW,
                                               const float* __restrict__ lb) {
    const int b = blockIdx.x, tid = threadIdx.x;
    __shared__ float spn[512];
    __shared__ float red[3][512];
    {
        const int kb = tid >> 7, l = tid & 127;
        spn[tid] = d_sp[(size_t)(kb * B + b) * L + l] / d_spsum[kb * B + b];
    }
    __syncthreads();
    float a0 = 0.f, a1 = 0.f, a2 = 0.f, a3 = 0.f;
    const float* c = d_ctx + (size_t)b * L * H + tid;
    for (int l = 0; l < 128; l++) {
        float cv = c[(size_t)l * H];
        a0 += spn[l] * cv; a1 += spn[128 + l] * cv;
        a2 += spn[256 + l] * cv; a3 += spn[384 + l] * cv;
    }
    float p0 = 0.f, p1 = 0.f, p2 = 0.f, s;
    s = fmaxf(a0, 0.f); p0 += s * lW[tid];        p1 += s * lW[2048 + tid];        p2 += s * lW[4096 + tid];
    s = fmaxf(a1, 0.f); p0 += s * lW[512 + tid];  p1 += s * lW[2560 + tid];        p2 += s * lW[4608 + tid];
    s = fmaxf(a2, 0.f); p0 += s * lW[1024 + tid]; p1 += s * lW[3072 + tid];        p2 += s * lW[5120 + tid];
    s = fmaxf(a3, 0.f); p0 += s * lW[1536 + tid]; p1 += s * lW[3584 + tid];        p2 += s * lW[5632 + tid];
    red[0][tid] = p0; red[1][tid] = p1; red[2][tid] = p2;
    __syncthreads();
    for (int off = 256; off > 0; off >>= 1) {
        if (tid < off) {
            red[0][tid] += red[0][tid + off];
            red[1][tid] += red[1][tid + off];
            red[2][tid] += red[2][tid + off];
        }
        __syncthreads();
    }
    if (tid < 3) d_scores[b * 3 + tid] = red[tid][0] + lb[tid];
}

__global__ void __launch_bounds__(128) loss_kernel(const int* __restrict__ labels,
                                                   float* __restrict__ out) {
    __shared__ float red[128];
    const int b = threadIdx.x;
    float s0 = d_scores[b * 3], s1 = d_scores[b * 3 + 1], s2 = d_scores[b * 3 + 2];
    float m = fmaxf(s0, fmaxf(s1, s2));
    float lse = m + logf(expf(s0 - m) + expf(s1 - m) + expf(s2 - m));
    int lab = labels[b];
    float sl = (lab == 0) ? s0 : ((lab == 1) ? s1 : s2);
    red[b] = lse - sl;
    __syncthreads();
    for (int off = 64; off > 0; off >>= 1) {
        if (b < off) red[b] += red[b + off];
        __syncthreads();
    }
    if (b == 0) out[0] = red[0] / (float)B;
}

extern "C" void kernel_launch(void* const* d_in, const int* in_sizes, int n_in,
                              void* d_out, int out_size) {
    (void)in_sizes; (void)n_in; (void)out_size;
    const float* sents = (const float*)d_in[0];
    const float* mtab  = (const float*)d_in[1];
    const float* gWihf = (const float*)d_in[2];
    const float* gWhhf = (const float*)d_in[3];
    const float* gbihf = (const float*)d_in[4];
    const float* gbhhf = (const float*)d_in[5];
    const float* gWihb = (const float*)d_in[6];
    const float* gWhhb = (const float*)d_in[7];
    const float* gbihb = (const float*)d_in[8];
    const float* gbhhb = (const float*)d_in[9];
    const float* hW    = (const float*)d_in[10];
    const float* hb    = (const float*)d_in[11];
    const float* tW    = (const float*)d_in[12];
    const float* tb    = (const float*)d_in[13];
    const float* trans = (const float*)d_in[14];
    const float* lW    = (const float*)d_in[15];
    const float* lb    = (const float*)d_in[16];
    const int* masks   = (const int*)d_in[17];
    const int* lens    = (const int*)d_in[18];
    const int* labels  = (const int*)d_in[19];
    float* out = (float*)d_out;

    const int smem_gru = (96 * 260 + 16 * 260 + 16 * 36 + 128 * 13) * 4 + 16 * 4;
    cudaFuncSetAttribute(gru_v5, cudaFuncAttributeMaxDynamicSharedMemorySize, smem_gru);
    const int smem_fk = (16 * 516 + 16 * 520) * 4;
    cudaFuncSetAttribute(fk2, cudaFuncAttributeMaxDynamicSharedMemorySize, smem_fk);

    prep_all<<<NB_MAIN + NB_Z, 128>>>(sents, mtab, masks, lens, gWihf, gWihb);  // 1
    prep_small<<<33, 256>>>(hW, tW, hb, tb);                                     // 2
    gemm_gi_bf16<<<dim3(6, 128, 2), 256>>>(gbihf, gbihb);                        // 3
    gru_v5<<<128, 256, smem_gru>>>(lens, gWhhf, gWhhb, gbhhf, gbhhb);            // 4 <- ncu
    fk2<<<128, 256, smem_fk>>>();                                                // 5
    crf_kernel<<<64, 32>>>(lens, trans);                                         // 6
    poolcls<<<B, 512>>>(lW, lb);                                                 // 7
    loss_kernel<<<1, 128>>>(labels, out);                                        // 8
}